// round 1
// baseline (speedup 1.0000x reference)
#include <cuda_runtime.h>
#include <math.h>

#define DIM   1024
#define HEADS 16
#define DH    64
#define INNER 1024
#define BATCH 4
#define SEQ   2048
#define T     (BATCH * SEQ)   // 8192 tokens

// ---------------- scratch (device globals; no allocations allowed) ----------
__device__ float g_xn [T * DIM];            // 32 MB
__device__ float g_qkv[T * 3 * INNER];      // 96 MB
__device__ float g_att[T * INNER];          // 32 MB

// ---------------- LayerNorm --------------------------------------------------
__global__ void ln_kernel(const float* __restrict__ x,
                          const float* __restrict__ gamma,
                          const float* __restrict__ beta,
                          float* __restrict__ xn) {
    int t = blockIdx.x, tid = threadIdx.x;  // 256 threads, 4 floats each
    const float4 v = ((const float4*)(x + (size_t)t * DIM))[tid];
    float s  = v.x + v.y + v.z + v.w;
    float ss = v.x * v.x + v.y * v.y + v.z * v.z + v.w * v.w;
#pragma unroll
    for (int o = 16; o; o >>= 1) {
        s  += __shfl_xor_sync(0xffffffffu, s,  o);
        ss += __shfl_xor_sync(0xffffffffu, ss, o);
    }
    __shared__ float rs[8], rq[8], stats[2];
    if ((tid & 31) == 0) { rs[tid >> 5] = s; rq[tid >> 5] = ss; }
    __syncthreads();
    if (tid == 0) {
        float a = 0.f, b2 = 0.f;
#pragma unroll
        for (int i = 0; i < 8; i++) { a += rs[i]; b2 += rq[i]; }
        float mu  = a * (1.f / DIM);
        float var = b2 * (1.f / DIM) - mu * mu;
        stats[0] = mu; stats[1] = rsqrtf(var + 1e-5f);
    }
    __syncthreads();
    float mu = stats[0], inv = stats[1];
    const float4 g  = ((const float4*)gamma)[tid];
    const float4 be = ((const float4*)beta)[tid];
    float4 o;
    o.x = (v.x - mu) * inv * g.x + be.x;
    o.y = (v.y - mu) * inv * g.y + be.y;
    o.z = (v.z - mu) * inv * g.z + be.z;
    o.w = (v.w - mu) * inv * g.w + be.w;
    ((float4*)(xn + (size_t)t * DIM))[tid] = o;
}

// ---------------- SGEMM: C[M,N] = A[M,K] @ B[K,N] (+bias) -------------------
// BM=BN=128, BK=8, 256 threads, 8x8 per thread. All dims divisible.
template <bool HAS_BIAS>
__global__ __launch_bounds__(256)
void sgemm_kernel(const float* __restrict__ A, const float* __restrict__ B,
                  const float* __restrict__ bias, float* __restrict__ C,
                  int M, int N, int K) {
    __shared__ float As[8][128];
    __shared__ float Bs[8][128];
    const int tid  = threadIdx.x;
    const int brow = blockIdx.y, bcol = blockIdx.x;
    const int aRow  = tid >> 1;            // 0..127
    const int aCol4 = (tid & 1) * 4;       // 0 or 4
    const int bRow  = tid >> 5;            // 0..7
    const int bCol4 = (tid & 31) * 4;      // 0..124
    const int tr = (tid >> 4) * 8, tc = (tid & 15) * 8;

    const float* Ap = A + (size_t)(brow * 128) * K;
    const float* Bp = B + (size_t)(bcol * 128);
    float acc[8][8] = {};

    for (int k0 = 0; k0 < K; k0 += 8) {
        float4 a = *(const float4*)(Ap + (size_t)aRow * K + k0 + aCol4);
        As[aCol4 + 0][aRow] = a.x;
        As[aCol4 + 1][aRow] = a.y;
        As[aCol4 + 2][aRow] = a.z;
        As[aCol4 + 3][aRow] = a.w;
        *(float4*)&Bs[bRow][bCol4] =
            *(const float4*)(Bp + (size_t)(k0 + bRow) * N + bCol4);
        __syncthreads();
#pragma unroll
        for (int kk = 0; kk < 8; kk++) {
            float ra[8], rb[8];
#pragma unroll
            for (int i = 0; i < 8; i += 4)
                *(float4*)&ra[i] = *(const float4*)&As[kk][tr + i];
#pragma unroll
            for (int j = 0; j < 8; j += 4)
                *(float4*)&rb[j] = *(const float4*)&Bs[kk][tc + j];
#pragma unroll
            for (int i = 0; i < 8; i++)
#pragma unroll
                for (int j = 0; j < 8; j++) acc[i][j] += ra[i] * rb[j];
        }
        __syncthreads();
    }

    float bj[8];
    if (HAS_BIAS) {
#pragma unroll
        for (int j = 0; j < 8; j++) bj[j] = bias[bcol * 128 + tc + j];
    }
    float* Cp = C + (size_t)(brow * 128 + tr) * N + bcol * 128 + tc;
#pragma unroll
    for (int i = 0; i < 8; i++) {
#pragma unroll
        for (int j = 0; j < 8; j += 4) {
            float4 o;
            o.x = acc[i][j + 0]; o.y = acc[i][j + 1];
            o.z = acc[i][j + 2]; o.w = acc[i][j + 3];
            if (HAS_BIAS) { o.x += bj[j]; o.y += bj[j+1]; o.z += bj[j+2]; o.w += bj[j+3]; }
            *(float4*)(Cp + (size_t)i * N + j) = o;
        }
    }
}

// ---------------- RoPE (in-place on q and k halves of qkv) ------------------
__global__ void rope_kernel(float* __restrict__ qkv) {
    int idx = blockIdx.x * blockDim.x + threadIdx.x;  // T*HEADS*32
    if (idx >= T * HEADS * 32) return;
    int i = idx & 31;           // frequency pair index
    int h = (idx >> 5) & (HEADS - 1);
    int t = idx >> 9;
    int pos = t & (SEQ - 1);
    // inv = 10000^(-i/32) computed as exp2(-i/32 * log2(10000))
    float inv = exp2f(-(float)i * (13.287712379549449f / 32.f));
    float ang = (float)pos * inv;
    float c, s;
    sincosf(ang, &s, &c);  // NOTE: sincosf(x, &sin, &cos)
    size_t base = (size_t)t * (3 * INNER) + h * DH + 2 * i;
    float e = qkv[base], o = qkv[base + 1];
    qkv[base]     = e * c - o * s;
    qkv[base + 1] = e * s + o * c;
    float e2 = qkv[base + INNER], o2 = qkv[base + INNER + 1];
    qkv[base + INNER]     = e2 * c - o2 * s;
    qkv[base + INNER + 1] = e2 * s + o2 * c;
}

// ---------------- Flash attention (fp32, non-causal) ------------------------
// Block: 64 queries x full KV stream in tiles of 32. 256 threads.
__global__ __launch_bounds__(256)
void attn_kernel(const float* __restrict__ qkv, float* __restrict__ att) {
    __shared__ float Qs[64][66];
    __shared__ float Ks[32][66];
    __shared__ float Vs[32][66];
    __shared__ float Ps[64][33];

    const int tid = threadIdx.x;
    const int tx = tid & 15, ty = tid >> 4;
    const int b = blockIdx.z, h = blockIdx.y;
    const int q0 = blockIdx.x * 64;

    const size_t qbase = ((size_t)(b * SEQ + q0)) * (3 * INNER) + h * DH;
    const size_t kbase = ((size_t)(b * SEQ)) * (3 * INNER) + INNER + h * DH;
    const size_t vbase = ((size_t)(b * SEQ)) * (3 * INNER) + 2 * INNER + h * DH;

    for (int f = tid; f < 64 * DH; f += 256) {
        int r = f >> 6, c = f & 63;
        Qs[r][c] = qkv[qbase + (size_t)r * (3 * INNER) + c];
    }

    float m_[4], l_[4], o_[4][4];
#pragma unroll
    for (int i = 0; i < 4; i++) {
        m_[i] = -1e30f; l_[i] = 0.f;
#pragma unroll
        for (int j = 0; j < 4; j++) o_[i][j] = 0.f;
    }
    const float scale = 0.125f;  // 64^-0.5

    for (int j0 = 0; j0 < SEQ; j0 += 32) {
        __syncthreads();  // protect Ks/Vs/Ps from prior readers (and Q load at iter 0)
        for (int f = tid; f < 32 * DH; f += 256) {
            int r = f >> 6, c = f & 63;
            Ks[r][c] = qkv[kbase + (size_t)(j0 + r) * (3 * INNER) + c];
            Vs[r][c] = qkv[vbase + (size_t)(j0 + r) * (3 * INNER) + c];
        }
        __syncthreads();

        // S = Q K^T : rows ty*4.., cols tx*2..
        float s[4][2] = {};
#pragma unroll
        for (int d = 0; d < DH; d++) {
            float k0v = Ks[tx * 2][d], k1v = Ks[tx * 2 + 1][d];
#pragma unroll
            for (int i = 0; i < 4; i++) {
                float qv = Qs[ty * 4 + i][d];
                s[i][0] += qv * k0v;
                s[i][1] += qv * k1v;
            }
        }
        // online softmax (row stats reduced over the 16-lane tx group)
#pragma unroll
        for (int i = 0; i < 4; i++) {
            s[i][0] *= scale; s[i][1] *= scale;
            float rmax = fmaxf(s[i][0], s[i][1]);
#pragma unroll
            for (int o = 8; o; o >>= 1)
                rmax = fmaxf(rmax, __shfl_xor_sync(0xffffffffu, rmax, o));
            float mnew  = fmaxf(m_[i], rmax);
            float alpha = __expf(m_[i] - mnew);
            float p0 = __expf(s[i][0] - mnew);
            float p1 = __expf(s[i][1] - mnew);
            float rsum = p0 + p1;
#pragma unroll
            for (int o = 8; o; o >>= 1)
                rsum += __shfl_xor_sync(0xffffffffu, rsum, o);
            l_[i] = l_[i] * alpha + rsum;
            m_[i] = mnew;
#pragma unroll
            for (int j = 0; j < 4; j++) o_[i][j] *= alpha;
            Ps[ty * 4 + i][tx * 2]     = p0;
            Ps[ty * 4 + i][tx * 2 + 1] = p1;
        }
        __syncthreads();

        // O += P V : rows ty*4.., d-cols tx*4..
#pragma unroll
        for (int n = 0; n < 32; n++) {
            float pv[4], vv[4];
#pragma unroll
            for (int i = 0; i < 4; i++) pv[i] = Ps[ty * 4 + i][n];
#pragma unroll
            for (int j = 0; j < 4; j++) vv[j] = Vs[n][tx * 4 + j];
#pragma unroll
            for (int i = 0; i < 4; i++)
#pragma unroll
                for (int j = 0; j < 4; j++) o_[i][j] += pv[i] * vv[j];
        }
    }

#pragma unroll
    for (int i = 0; i < 4; i++) {
        float invl = 1.f / l_[i];
        size_t ob = ((size_t)(b * SEQ + q0 + ty * 4 + i)) * INNER + h * DH + tx * 4;
#pragma unroll
        for (int j = 0; j < 4; j++) att[ob + j] = o_[i][j] * invl;
    }
}

// ---------------- launch -----------------------------------------------------
extern "C" void kernel_launch(void* const* d_in, const int* in_sizes, int n_in,
                              void* d_out, int out_size) {
    const float* x     = (const float*)d_in[0];
    const float* gamma = (const float*)d_in[1];
    const float* beta  = (const float*)d_in[2];
    const float* w_qkv = (const float*)d_in[3];
    const float* w_out = (const float*)d_in[4];
    const float* b_out = (const float*)d_in[5];
    float* out = (float*)d_out;

    float *xn, *qkv, *att;
    cudaGetSymbolAddress((void**)&xn,  g_xn);
    cudaGetSymbolAddress((void**)&qkv, g_qkv);
    cudaGetSymbolAddress((void**)&att, g_att);

    // 1) LayerNorm
    ln_kernel<<<T, 256>>>(x, gamma, beta, xn);
    // 2) QKV projection: [8192,1024] @ [1024,3072]
    sgemm_kernel<false><<<dim3(3 * INNER / 128, T / 128), 256>>>(
        xn, w_qkv, nullptr, qkv, T, 3 * INNER, DIM);
    // 3) RoPE on q,k
    rope_kernel<<<(T * HEADS * 32 + 255) / 256, 256>>>(qkv);
    // 4) Attention
    attn_kernel<<<dim3(SEQ / 64, HEADS, BATCH), 256>>>(qkv, att);
    // 5) Output projection + bias: [8192,1024] @ [1024,1024]
    sgemm_kernel<true><<<dim3(DIM / 128, T / 128), 256>>>(
        att, w_out, b_out, out, T, DIM, INNER);
}

// round 5
// speedup vs baseline: 2.2201x; 2.2201x over previous
#include <cuda_runtime.h>
#include <cuda_bf16.h>
#include <math.h>
#include <stdint.h>

#define DIM   1024
#define HEADS 16
#define DH    64
#define INNER 1024
#define BATCH 4
#define SEQ   2048
#define T     (BATCH * SEQ)   // 8192 tokens

typedef __nv_bfloat16 bf16;

// ---------------- scratch (device globals) ----------------------------------
__device__ bf16  g_xn_hi[T * DIM],        g_xn_lo[T * DIM];
__device__ bf16  g_wqt_hi[3 * INNER * DIM], g_wqt_lo[3 * INNER * DIM]; // [N][K]
__device__ bf16  g_wot_hi[DIM * INNER],   g_wot_lo[DIM * INNER];       // [N][K]
__device__ float g_qkv[T * 3 * INNER];
__device__ bf16  g_q_hi[T * INNER], g_q_lo[T * INNER];  // [b][h][n][d]
__device__ bf16  g_k_hi[T * INNER], g_k_lo[T * INNER];
__device__ bf16  g_v_hi[T * INNER], g_v_lo[T * INNER];
__device__ bf16  g_att_hi[T * INNER], g_att_lo[T * INNER]; // [t][h*64+d]

// ---------------- helpers ----------------------------------------------------
__device__ __forceinline__ uint32_t pack2(bf16 a, bf16 b) {
    return (uint32_t)__bfloat16_as_ushort(a) |
           ((uint32_t)__bfloat16_as_ushort(b) << 16);
}
__device__ __forceinline__ void split2(float x, bf16& h, bf16& l) {
    h = __float2bfloat16(x);
    l = __float2bfloat16(x - __bfloat162float(h));
}
__device__ __forceinline__ uint32_t hi2(float a, float b) {
    return pack2(__float2bfloat16(a), __float2bfloat16(b));
}
__device__ __forceinline__ uint32_t lo2(float a, float b) {
    bf16 ha = __float2bfloat16(a), hb = __float2bfloat16(b);
    return pack2(__float2bfloat16(a - __bfloat162float(ha)),
                 __float2bfloat16(b - __bfloat162float(hb)));
}
__device__ __forceinline__ void mma16816(float c[4], const uint32_t a[4],
                                         const uint32_t b[2]) {
    asm volatile(
        "mma.sync.aligned.m16n8k16.row.col.f32.bf16.bf16.f32 "
        "{%0,%1,%2,%3}, {%4,%5,%6,%7}, {%8,%9}, {%0,%1,%2,%3};\n"
        : "+f"(c[0]), "+f"(c[1]), "+f"(c[2]), "+f"(c[3])
        : "r"(a[0]), "r"(a[1]), "r"(a[2]), "r"(a[3]), "r"(b[0]), "r"(b[1]));
}

// ---------------- LayerNorm -> split bf16 ------------------------------------
__global__ void ln_split_kernel(const float* __restrict__ x,
                                const float* __restrict__ gamma,
                                const float* __restrict__ beta,
                                bf16* __restrict__ xh, bf16* __restrict__ xl) {
    int t = blockIdx.x, tid = threadIdx.x;
    const float4 v = ((const float4*)(x + (size_t)t * DIM))[tid];
    float s  = v.x + v.y + v.z + v.w;
    float ss = v.x * v.x + v.y * v.y + v.z * v.z + v.w * v.w;
#pragma unroll
    for (int o = 16; o; o >>= 1) {
        s  += __shfl_xor_sync(0xffffffffu, s,  o);
        ss += __shfl_xor_sync(0xffffffffu, ss, o);
    }
    __shared__ float rs[8], rq[8], stats[2];
    if ((tid & 31) == 0) { rs[tid >> 5] = s; rq[tid >> 5] = ss; }
    __syncthreads();
    if (tid == 0) {
        float a = 0.f, b2 = 0.f;
#pragma unroll
        for (int i = 0; i < 8; i++) { a += rs[i]; b2 += rq[i]; }
        float mu  = a * (1.f / DIM);
        float var = b2 * (1.f / DIM) - mu * mu;
        stats[0] = mu; stats[1] = rsqrtf(var + 1e-5f);
    }
    __syncthreads();
    float mu = stats[0], inv = stats[1];
    const float4 g  = ((const float4*)gamma)[tid];
    const float4 be = ((const float4*)beta)[tid];
    float o0 = (v.x - mu) * inv * g.x + be.x;
    float o1 = (v.y - mu) * inv * g.y + be.y;
    float o2 = (v.z - mu) * inv * g.z + be.z;
    float o3 = (v.w - mu) * inv * g.w + be.w;
    size_t o = (size_t)t * DIM + tid * 4;
    uint2 h = make_uint2(hi2(o0, o1), hi2(o2, o3));
    uint2 l = make_uint2(lo2(o0, o1), lo2(o2, o3));
    *(uint2*)&xh[o] = h;
    *(uint2*)&xl[o] = l;
}

// ---------------- transpose + split weights ----------------------------------
// w [K][N] (row-major) -> wt_hi/lo [N][K]
__global__ void transpose_split_kernel(const float* __restrict__ w,
                                       bf16* __restrict__ wh,
                                       bf16* __restrict__ wl, int K, int N) {
    __shared__ float tile[32][33];
    int n0 = blockIdx.x * 32, k0 = blockIdx.y * 32;
    int tx = threadIdx.x, ty = threadIdx.y;  // 32 x 8
#pragma unroll
    for (int i = 0; i < 32; i += 8)
        tile[ty + i][tx] = w[(size_t)(k0 + ty + i) * N + n0 + tx];
    __syncthreads();
#pragma unroll
    for (int i = 0; i < 32; i += 8) {
        float v = tile[tx][ty + i];
        bf16 h, l; split2(v, h, l);
        size_t o = (size_t)(n0 + ty + i) * K + k0 + tx;
        wh[o] = h; wl[o] = l;
    }
}

// ---------------- bf16x3 GEMM: C[M,N] = A[M,K] @ Bt[N,K]^T (+bias) ----------
// BM=BN=128, BK=32, 256 threads (8 warps, 4x2), warp tile 32x64.
template <bool HAS_BIAS>
__global__ __launch_bounds__(256)
void gemm_kernel(const bf16* __restrict__ Agh, const bf16* __restrict__ Agl,
                 const bf16* __restrict__ Bgh, const bf16* __restrict__ Bgl,
                 const float* __restrict__ bias, float* __restrict__ C,
                 int M, int N, int K) {
    __shared__ bf16 sAh[128][40], sAl[128][40], sBh[128][40], sBl[128][40];
    const int tid = threadIdx.x;
    const int wid = tid >> 5, lane = tid & 31;
    const int wm = wid >> 1, wn = wid & 1;
    const int g = lane >> 2, t2 = (lane & 3) * 2;
    const int m0 = blockIdx.y * 128, n0 = blockIdx.x * 128;
    const int lrow = tid >> 1, lcol = (tid & 1) * 16;

    float acc[2][8][4];
#pragma unroll
    for (int i = 0; i < 2; i++)
#pragma unroll
        for (int j = 0; j < 8; j++)
#pragma unroll
            for (int k = 0; k < 4; k++) acc[i][j][k] = 0.f;

    uint4 pf[8];
    auto gload = [&](int k0) {
        const bf16* pa = Agh + (size_t)(m0 + lrow) * K + k0 + lcol;
        pf[0] = *(const uint4*)pa; pf[1] = *(const uint4*)(pa + 8);
        pa = Agl + (size_t)(m0 + lrow) * K + k0 + lcol;
        pf[2] = *(const uint4*)pa; pf[3] = *(const uint4*)(pa + 8);
        pa = Bgh + (size_t)(n0 + lrow) * K + k0 + lcol;
        pf[4] = *(const uint4*)pa; pf[5] = *(const uint4*)(pa + 8);
        pa = Bgl + (size_t)(n0 + lrow) * K + k0 + lcol;
        pf[6] = *(const uint4*)pa; pf[7] = *(const uint4*)(pa + 8);
    };
    gload(0);

    for (int k0 = 0; k0 < K; k0 += 32) {
        __syncthreads();
        *(uint4*)&sAh[lrow][lcol] = pf[0]; *(uint4*)&sAh[lrow][lcol + 8] = pf[1];
        *(uint4*)&sAl[lrow][lcol] = pf[2]; *(uint4*)&sAl[lrow][lcol + 8] = pf[3];
        *(uint4*)&sBh[lrow][lcol] = pf[4]; *(uint4*)&sBh[lrow][lcol + 8] = pf[5];
        *(uint4*)&sBl[lrow][lcol] = pf[6]; *(uint4*)&sBl[lrow][lcol + 8] = pf[7];
        __syncthreads();
        if (k0 + 32 < K) gload(k0 + 32);

#pragma unroll
        for (int kk = 0; kk < 32; kk += 16) {
            uint32_t aH[2][4], aL[2][4], bH[8][2], bL[8][2];
#pragma unroll
            for (int mt = 0; mt < 2; mt++) {
                int r = wm * 32 + mt * 16;
                aH[mt][0] = *(const uint32_t*)&sAh[r + g][kk + t2];
                aH[mt][1] = *(const uint32_t*)&sAh[r + g + 8][kk + t2];
                aH[mt][2] = *(const uint32_t*)&sAh[r + g][kk + t2 + 8];
                aH[mt][3] = *(const uint32_t*)&sAh[r + g + 8][kk + t2 + 8];
                aL[mt][0] = *(const uint32_t*)&sAl[r + g][kk + t2];
                aL[mt][1] = *(const uint32_t*)&sAl[r + g + 8][kk + t2];
                aL[mt][2] = *(const uint32_t*)&sAl[r + g][kk + t2 + 8];
                aL[mt][3] = *(const uint32_t*)&sAl[r + g + 8][kk + t2 + 8];
            }
#pragma unroll
            for (int nt = 0; nt < 8; nt++) {
                int c = wn * 64 + nt * 8 + g;
                bH[nt][0] = *(const uint32_t*)&sBh[c][kk + t2];
                bH[nt][1] = *(const uint32_t*)&sBh[c][kk + t2 + 8];
                bL[nt][0] = *(const uint32_t*)&sBl[c][kk + t2];
                bL[nt][1] = *(const uint32_t*)&sBl[c][kk + t2 + 8];
            }
#pragma unroll
            for (int mt = 0; mt < 2; mt++)
#pragma unroll
                for (int nt = 0; nt < 8; nt++) {
                    mma16816(acc[mt][nt], aH[mt], bH[nt]);
                    mma16816(acc[mt][nt], aH[mt], bL[nt]);
                    mma16816(acc[mt][nt], aL[mt], bH[nt]);
                }
        }
    }

#pragma unroll
    for (int mt = 0; mt < 2; mt++) {
#pragma unroll
        for (int nt = 0; nt < 8; nt++) {
            int row = m0 + wm * 32 + mt * 16 + g;
            int col = n0 + wn * 64 + nt * 8 + t2;
            float b0 = 0.f, b1 = 0.f;
            if (HAS_BIAS) { b0 = bias[col]; b1 = bias[col + 1]; }
            float2 v0 = make_float2(acc[mt][nt][0] + b0, acc[mt][nt][1] + b1);
            float2 v1 = make_float2(acc[mt][nt][2] + b0, acc[mt][nt][3] + b1);
            *(float2*)&C[(size_t)row * N + col] = v0;
            *(float2*)&C[(size_t)(row + 8) * N + col] = v1;
        }
    }
}

// ---------------- RoPE + split + head-major relayout -------------------------
__global__ void rope_convert_kernel(const float* __restrict__ qkv,
                                    bf16* __restrict__ qh, bf16* __restrict__ ql,
                                    bf16* __restrict__ kh, bf16* __restrict__ kl,
                                    bf16* __restrict__ vh, bf16* __restrict__ vl) {
    int idx = blockIdx.x * 256 + threadIdx.x;
    if (idx >= T * HEADS * 32) return;
    int i = idx & 31;
    int h = (idx >> 5) & (HEADS - 1);
    int t = idx >> 9;
    int pos = t & (SEQ - 1);
    int b = t >> 11;
    float inv = exp2f(-(float)i * (13.287712379549449f / 32.f));
    float ang = (float)pos * inv;
    float sn, cs;
    sincosf(ang, &sn, &cs);
    size_t base = (size_t)t * (3 * INNER) + h * DH + 2 * i;
    float qe = qkv[base],        qo = qkv[base + 1];
    float ke = qkv[base + INNER], ko = qkv[base + INNER + 1];
    float v0 = qkv[base + 2 * INNER], v1 = qkv[base + 2 * INNER + 1];
    float q0 = qe * cs - qo * sn, q1 = qe * sn + qo * cs;
    float k0 = ke * cs - ko * sn, k1 = ke * sn + ko * cs;
    size_t o = (((size_t)(b * HEADS + h)) * SEQ + pos) * DH + 2 * i;
    *(uint32_t*)&qh[o] = hi2(q0, q1); *(uint32_t*)&ql[o] = lo2(q0, q1);
    *(uint32_t*)&kh[o] = hi2(k0, k1); *(uint32_t*)&kl[o] = lo2(k0, k1);
    *(uint32_t*)&vh[o] = hi2(v0, v1); *(uint32_t*)&vl[o] = lo2(v0, v1);
}

// ---------------- Flash attention (bf16x3 tensor-core) ----------------------
// Block: 128 q-rows, 8 warps (16 rows each). KV chunks of 64.
__global__ __launch_bounds__(256)
void attn_kernel(const bf16* __restrict__ qgh, const bf16* __restrict__ qgl,
                 const bf16* __restrict__ kgh, const bf16* __restrict__ kgl,
                 const bf16* __restrict__ vgh, const bf16* __restrict__ vgl,
                 bf16* __restrict__ oh, bf16* __restrict__ ol) {
    extern __shared__ __align__(16) unsigned char smraw[];
    bf16 (*Qh)[72]  = (bf16(*)[72])smraw;   // 128 x 72
    bf16 (*Ql)[72]  = Qh + 128;
    bf16 (*Kh)[72]  = Ql + 128;             // 64 x 72
    bf16 (*Kl)[72]  = Kh + 64;
    bf16 (*Vth)[72] = Kl + 64;              // 64(dh) x 72(tok pad)
    bf16 (*Vtl)[72] = Vth + 64;

    const int tid = threadIdx.x, wid = tid >> 5, lane = tid & 31;
    const int g = lane >> 2, t2 = (lane & 3) * 2;
    const int b = blockIdx.z, h = blockIdx.y;
    const int q0 = blockIdx.x * 128;
    const size_t hb = (size_t)(b * HEADS + h) * SEQ * DH;

    // Q tile load (hi/lo), 4 uint4 per array per thread
    {
        int r = tid >> 1, c = (tid & 1) * 32;
        const uint4* src = (const uint4*)(qgh + hb + (size_t)(q0 + r) * DH + c);
        uint4 x0 = src[0], x1 = src[1], x2 = src[2], x3 = src[3];
        *(uint4*)&Qh[r][c] = x0; *(uint4*)&Qh[r][c + 8] = x1;
        *(uint4*)&Qh[r][c + 16] = x2; *(uint4*)&Qh[r][c + 24] = x3;
        src = (const uint4*)(qgl + hb + (size_t)(q0 + r) * DH + c);
        x0 = src[0]; x1 = src[1]; x2 = src[2]; x3 = src[3];
        *(uint4*)&Ql[r][c] = x0; *(uint4*)&Ql[r][c + 8] = x1;
        *(uint4*)&Ql[r][c + 16] = x2; *(uint4*)&Ql[r][c + 24] = x3;
    }

    const int lr = tid >> 2, lc = (tid & 3) * 16;  // KV load map: 64 rows x 4
    uint4 kpf[4], vpf[4];
    auto loadK = [&](int j0) {
        const uint4* s1 = (const uint4*)(kgh + hb + (size_t)(j0 + lr) * DH + lc);
        kpf[0] = s1[0]; kpf[1] = s1[1];
        const uint4* s2 = (const uint4*)(kgl + hb + (size_t)(j0 + lr) * DH + lc);
        kpf[2] = s2[0]; kpf[3] = s2[1];
    };
    auto loadV = [&](int j0) {
        const uint4* s1 = (const uint4*)(vgh + hb + (size_t)(j0 + lr) * DH + lc);
        vpf[0] = s1[0]; vpf[1] = s1[1];
        const uint4* s2 = (const uint4*)(vgl + hb + (size_t)(j0 + lr) * DH + lc);
        vpf[2] = s2[0]; vpf[3] = s2[1];
    };
    loadK(0); loadV(0);

    float m0v = -1e30f, m1v = -1e30f, l0v = 0.f, l1v = 0.f;
    float oacc[8][4];
#pragma unroll
    for (int i = 0; i < 8; i++)
#pragma unroll
        for (int j = 0; j < 4; j++) oacc[i][j] = 0.f;

    const int qr = wid * 16;

    for (int j0 = 0; j0 < SEQ; j0 += 64) {
        __syncthreads();  // prev chunk's readers of Kh/Vt done; Q loaded (iter 0)
        // store K tile
        *(uint4*)&Kh[lr][lc] = kpf[0]; *(uint4*)&Kh[lr][lc + 8] = kpf[1];
        *(uint4*)&Kl[lr][lc] = kpf[2]; *(uint4*)&Kl[lr][lc + 8] = kpf[3];
        // store V transposed: element e of row lr at dh col lc+e
        {
            uint32_t w[8] = {vpf[0].x, vpf[0].y, vpf[0].z, vpf[0].w,
                             vpf[1].x, vpf[1].y, vpf[1].z, vpf[1].w};
#pragma unroll
            for (int e = 0; e < 8; e++) {
                *(unsigned short*)&Vth[lc + 2 * e][lr]     = (unsigned short)(w[e] & 0xffff);
                *(unsigned short*)&Vth[lc + 2 * e + 1][lr] = (unsigned short)(w[e] >> 16);
            }
            uint32_t u[8] = {vpf[2].x, vpf[2].y, vpf[2].z, vpf[2].w,
                             vpf[3].x, vpf[3].y, vpf[3].z, vpf[3].w};
#pragma unroll
            for (int e = 0; e < 8; e++) {
                *(unsigned short*)&Vtl[lc + 2 * e][lr]     = (unsigned short)(u[e] & 0xffff);
                *(unsigned short*)&Vtl[lc + 2 * e + 1][lr] = (unsigned short)(u[e] >> 16);
            }
        }
        __syncthreads();
        if (j0 + 64 < SEQ) { loadK(j0 + 64); loadV(j0 + 64); }

        // ---- S = Q K^T over 64-wide chunk ----
        float sacc[8][4];
#pragma unroll
        for (int i = 0; i < 8; i++)
#pragma unroll
            for (int j = 0; j < 4; j++) sacc[i][j] = 0.f;
#pragma unroll
        for (int kk = 0; kk < 64; kk += 16) {
            uint32_t aH[4], aL[4], bH[8][2], bL[8][2];
            aH[0] = *(const uint32_t*)&Qh[qr + g][kk + t2];
            aH[1] = *(const uint32_t*)&Qh[qr + g + 8][kk + t2];
            aH[2] = *(const uint32_t*)&Qh[qr + g][kk + t2 + 8];
            aH[3] = *(const uint32_t*)&Qh[qr + g + 8][kk + t2 + 8];
            aL[0] = *(const uint32_t*)&Ql[qr + g][kk + t2];
            aL[1] = *(const uint32_t*)&Ql[qr + g + 8][kk + t2];
            aL[2] = *(const uint32_t*)&Ql[qr + g][kk + t2 + 8];
            aL[3] = *(const uint32_t*)&Ql[qr + g + 8][kk + t2 + 8];
#pragma unroll
            for (int nt = 0; nt < 8; nt++) {
                bH[nt][0] = *(const uint32_t*)&Kh[nt * 8 + g][kk + t2];
                bH[nt][1] = *(const uint32_t*)&Kh[nt * 8 + g][kk + t2 + 8];
                bL[nt][0] = *(const uint32_t*)&Kl[nt * 8 + g][kk + t2];
                bL[nt][1] = *(const uint32_t*)&Kl[nt * 8 + g][kk + t2 + 8];
            }
#pragma unroll
            for (int nt = 0; nt < 8; nt++) {
                mma16816(sacc[nt], aH, bH[nt]);
                mma16816(sacc[nt], aH, bL[nt]);
                mma16816(sacc[nt], aL, bH[nt]);
            }
        }

        // ---- online softmax (rows g and g+8; cols spread over tid4 group) ----
        const float scale = 0.125f;
        float mx0 = -1e30f, mx1 = -1e30f;
#pragma unroll
        for (int nt = 0; nt < 8; nt++) {
#pragma unroll
            for (int j = 0; j < 4; j++) sacc[nt][j] *= scale;
            mx0 = fmaxf(mx0, fmaxf(sacc[nt][0], sacc[nt][1]));
            mx1 = fmaxf(mx1, fmaxf(sacc[nt][2], sacc[nt][3]));
        }
#pragma unroll
        for (int o = 1; o <= 2; o <<= 1) {
            mx0 = fmaxf(mx0, __shfl_xor_sync(0xffffffffu, mx0, o));
            mx1 = fmaxf(mx1, __shfl_xor_sync(0xffffffffu, mx1, o));
        }
        float mn0 = fmaxf(m0v, mx0), mn1 = fmaxf(m1v, mx1);
        float al0 = __expf(m0v - mn0), al1 = __expf(m1v - mn1);
        float sum0 = 0.f, sum1 = 0.f;
#pragma unroll
        for (int nt = 0; nt < 8; nt++) {
            sacc[nt][0] = __expf(sacc[nt][0] - mn0);
            sacc[nt][1] = __expf(sacc[nt][1] - mn0);
            sacc[nt][2] = __expf(sacc[nt][2] - mn1);
            sacc[nt][3] = __expf(sacc[nt][3] - mn1);
            sum0 += sacc[nt][0] + sacc[nt][1];
            sum1 += sacc[nt][2] + sacc[nt][3];
        }
#pragma unroll
        for (int o = 1; o <= 2; o <<= 1) {
            sum0 += __shfl_xor_sync(0xffffffffu, sum0, o);
            sum1 += __shfl_xor_sync(0xffffffffu, sum1, o);
        }
        l0v = l0v * al0 + sum0; m0v = mn0;
        l1v = l1v * al1 + sum1; m1v = mn1;
#pragma unroll
        for (int nt = 0; nt < 8; nt++) {
            oacc[nt][0] *= al0; oacc[nt][1] *= al0;
            oacc[nt][2] *= al1; oacc[nt][3] *= al1;
        }

        // ---- O += P V ----
#pragma unroll
        for (int kt = 0; kt < 4; kt++) {
            uint32_t pH[4], pL[4];
            pH[0] = hi2(sacc[2 * kt][0],     sacc[2 * kt][1]);
            pH[1] = hi2(sacc[2 * kt][2],     sacc[2 * kt][3]);
            pH[2] = hi2(sacc[2 * kt + 1][0], sacc[2 * kt + 1][1]);
            pH[3] = hi2(sacc[2 * kt + 1][2], sacc[2 * kt + 1][3]);
            pL[0] = lo2(sacc[2 * kt][0],     sacc[2 * kt][1]);
            pL[1] = lo2(sacc[2 * kt][2],     sacc[2 * kt][3]);
            pL[2] = lo2(sacc[2 * kt + 1][0], sacc[2 * kt + 1][1]);
            pL[3] = lo2(sacc[2 * kt + 1][2], sacc[2 * kt + 1][3]);
            uint32_t bH[8][2], bL[8][2];
#pragma unroll
            for (int nt = 0; nt < 8; nt++) {
                bH[nt][0] = *(const uint32_t*)&Vth[nt * 8 + g][kt * 16 + t2];
                bH[nt][1] = *(const uint32_t*)&Vth[nt * 8 + g][kt * 16 + t2 + 8];
                bL[nt][0] = *(const uint32_t*)&Vtl[nt * 8 + g][kt * 16 + t2];
                bL[nt][1] = *(const uint32_t*)&Vtl[nt * 8 + g][kt * 16 + t2 + 8];
            }
#pragma unroll
            for (int nt = 0; nt < 8; nt++) {
                mma16816(oacc[nt], pH, bH[nt]);
                mma16816(oacc[nt], pH, bL[nt]);
                mma16816(oacc[nt], pL, bH[nt]);
            }
        }
    }

    // ---- epilogue: O/l, split, store [t][h*64+d] ----
    float i0 = 1.f / l0v, i1 = 1.f / l1v;
#pragma unroll
    for (int nt = 0; nt < 8; nt++) {
        int row = q0 + qr + g;
        int col = h * DH + nt * 8 + t2;
        size_t ob = (size_t)(b * SEQ + row) * INNER + col;
        float a0 = oacc[nt][0] * i0, a1 = oacc[nt][1] * i0;
        float a2 = oacc[nt][2] * i1, a3 = oacc[nt][3] * i1;
        *(uint32_t*)&oh[ob] = hi2(a0, a1);
        *(uint32_t*)&ol[ob] = lo2(a0, a1);
        size_t ob2 = ob + (size_t)8 * INNER;
        *(uint32_t*)&oh[ob2] = hi2(a2, a3);
        *(uint32_t*)&ol[ob2] = lo2(a2, a3);
    }
}

// ---------------- launch -----------------------------------------------------
extern "C" void kernel_launch(void* const* d_in, const int* in_sizes, int n_in,
                              void* d_out, int out_size) {
    const float* x     = (const float*)d_in[0];
    const float* gamma = (const float*)d_in[1];
    const float* beta  = (const float*)d_in[2];
    const float* w_qkv = (const float*)d_in[3];
    const float* w_out = (const float*)d_in[4];
    const float* b_out = (const float*)d_in[5];
    float* out = (float*)d_out;

    bf16 *xnh, *xnl, *wqh, *wql, *woh, *wol;
    bf16 *qh, *ql, *kh, *kl, *vh, *vl, *ah, *al;
    float* qkv;
    cudaGetSymbolAddress((void**)&xnh, g_xn_hi);
    cudaGetSymbolAddress((void**)&xnl, g_xn_lo);
    cudaGetSymbolAddress((void**)&wqh, g_wqt_hi);
    cudaGetSymbolAddress((void**)&wql, g_wqt_lo);
    cudaGetSymbolAddress((void**)&woh, g_wot_hi);
    cudaGetSymbolAddress((void**)&wol, g_wot_lo);
    cudaGetSymbolAddress((void**)&qkv, g_qkv);
    cudaGetSymbolAddress((void**)&qh, g_q_hi);
    cudaGetSymbolAddress((void**)&ql, g_q_lo);
    cudaGetSymbolAddress((void**)&kh, g_k_hi);
    cudaGetSymbolAddress((void**)&kl, g_k_lo);
    cudaGetSymbolAddress((void**)&vh, g_v_hi);
    cudaGetSymbolAddress((void**)&vl, g_v_lo);
    cudaGetSymbolAddress((void**)&ah, g_att_hi);
    cudaGetSymbolAddress((void**)&al, g_att_lo);

    cudaFuncSetAttribute(attn_kernel,
                         cudaFuncAttributeMaxDynamicSharedMemorySize, 73728);

    // 1) LayerNorm -> split bf16
    ln_split_kernel<<<T, 256>>>(x, gamma, beta, xnh, xnl);
    // 2) weight transposes + splits
    transpose_split_kernel<<<dim3(3 * INNER / 32, DIM / 32), dim3(32, 8)>>>(
        w_qkv, wqh, wql, DIM, 3 * INNER);
    transpose_split_kernel<<<dim3(DIM / 32, INNER / 32), dim3(32, 8)>>>(
        w_out, woh, wol, INNER, DIM);
    // 3) QKV GEMM (fp32 out)
    gemm_kernel<false><<<dim3(3 * INNER / 128, T / 128), 256>>>(
        xnh, xnl, wqh, wql, nullptr, qkv, T, 3 * INNER, DIM);
    // 4) RoPE + split + relayout
    rope_convert_kernel<<<(T * HEADS * 32 + 255) / 256, 256>>>(
        qkv, qh, ql, kh, kl, vh, vl);
    // 5) Attention (tensor-core bf16x3)
    attn_kernel<<<dim3(SEQ / 128, HEADS, BATCH), 256, 73728>>>(
        qh, ql, kh, kl, vh, vl, ah, al);
    // 6) Output projection + bias
    gemm_kernel<true><<<dim3(DIM / 128, T / 128), 256>>>(
        ah, al, woh, wol, b_out, out, T, DIM, INNER);
}

// round 9
// speedup vs baseline: 2.7055x; 1.2186x over previous
#include <cuda_runtime.h>
#include <cuda_bf16.h>
#include <math.h>
#include <stdint.h>

#define DIM   1024
#define HEADS 16
#define DH    64
#define INNER 1024
#define BATCH 4
#define SEQ   2048
#define T     (BATCH * SEQ)   // 8192 tokens

typedef __nv_bfloat16 bf16;

// ---------------- scratch (device globals) ----------------------------------
__device__ bf16  g_xn_hi[T * DIM],        g_xn_lo[T * DIM];
__device__ bf16  g_wqt_hi[3 * INNER * DIM], g_wqt_lo[3 * INNER * DIM]; // [N][K]
__device__ bf16  g_wot_hi[DIM * INNER],   g_wot_lo[DIM * INNER];       // [N][K]
__device__ float g_qkv[T * 3 * INNER];
__device__ bf16  g_q_hi[T * INNER], g_q_lo[T * INNER];  // [b][h][n][d]
__device__ bf16  g_k_hi[T * INNER], g_k_lo[T * INNER];
__device__ bf16  g_v_hi[T * INNER], g_v_lo[T * INNER];
__device__ bf16  g_att_hi[T * INNER], g_att_lo[T * INNER]; // [t][h*64+d]

// ---------------- helpers ----------------------------------------------------
__device__ __forceinline__ uint32_t pack2(bf16 a, bf16 b) {
    return (uint32_t)__bfloat16_as_ushort(a) |
           ((uint32_t)__bfloat16_as_ushort(b) << 16);
}
__device__ __forceinline__ void split2(float x, bf16& h, bf16& l) {
    h = __float2bfloat16(x);
    l = __float2bfloat16(x - __bfloat162float(h));
}
__device__ __forceinline__ uint32_t hi2(float a, float b) {
    return pack2(__float2bfloat16(a), __float2bfloat16(b));
}
__device__ __forceinline__ uint32_t lo2(float a, float b) {
    bf16 ha = __float2bfloat16(a), hb = __float2bfloat16(b);
    return pack2(__float2bfloat16(a - __bfloat162float(ha)),
                 __float2bfloat16(b - __bfloat162float(hb)));
}
__device__ __forceinline__ void mma16816(float c[4], const uint32_t a[4],
                                         const uint32_t b[2]) {
    asm volatile(
        "mma.sync.aligned.m16n8k16.row.col.f32.bf16.bf16.f32 "
        "{%0,%1,%2,%3}, {%4,%5,%6,%7}, {%8,%9}, {%0,%1,%2,%3};\n"
        : "+f"(c[0]), "+f"(c[1]), "+f"(c[2]), "+f"(c[3])
        : "r"(a[0]), "r"(a[1]), "r"(a[2]), "r"(a[3]), "r"(b[0]), "r"(b[1]));
}
__device__ __forceinline__ void ldsm4(uint32_t r[4], uint32_t addr) {
    asm volatile("ldmatrix.sync.aligned.m8n8.x4.shared.b16 {%0,%1,%2,%3}, [%4];"
        : "=r"(r[0]), "=r"(r[1]), "=r"(r[2]), "=r"(r[3]) : "r"(addr));
}
__device__ __forceinline__ void ldsm4t(uint32_t r[4], uint32_t addr) {
    asm volatile("ldmatrix.sync.aligned.m8n8.x4.trans.shared.b16 {%0,%1,%2,%3}, [%4];"
        : "=r"(r[0]), "=r"(r[1]), "=r"(r[2]), "=r"(r[3]) : "r"(addr));
}
__device__ __forceinline__ void cpa16(uint32_t dst, const void* src) {
    asm volatile("cp.async.cg.shared.global [%0], [%1], 16;" :: "r"(dst), "l"(src));
}
#define CP_COMMIT asm volatile("cp.async.commit_group;" ::: "memory")
#define CP_WAIT1  asm volatile("cp.async.wait_group 1;" ::: "memory")
#define CP_WAIT2  asm volatile("cp.async.wait_group 2;" ::: "memory")

// ---------------- LayerNorm -> split bf16 ------------------------------------
__global__ void ln_split_kernel(const float* __restrict__ x,
                                const float* __restrict__ gamma,
                                const float* __restrict__ beta,
                                bf16* __restrict__ xh, bf16* __restrict__ xl) {
    int t = blockIdx.x, tid = threadIdx.x;
    const float4 v = ((const float4*)(x + (size_t)t * DIM))[tid];
    float s  = v.x + v.y + v.z + v.w;
    float ss = v.x * v.x + v.y * v.y + v.z * v.z + v.w * v.w;
#pragma unroll
    for (int o = 16; o; o >>= 1) {
        s  += __shfl_xor_sync(0xffffffffu, s,  o);
        ss += __shfl_xor_sync(0xffffffffu, ss, o);
    }
    __shared__ float rs[8], rq[8], stats[2];
    if ((tid & 31) == 0) { rs[tid >> 5] = s; rq[tid >> 5] = ss; }
    __syncthreads();
    if (tid == 0) {
        float a = 0.f, b2 = 0.f;
#pragma unroll
        for (int i = 0; i < 8; i++) { a += rs[i]; b2 += rq[i]; }
        float mu  = a * (1.f / DIM);
        float var = b2 * (1.f / DIM) - mu * mu;
        stats[0] = mu; stats[1] = rsqrtf(var + 1e-5f);
    }
    __syncthreads();
    float mu = stats[0], inv = stats[1];
    const float4 g  = ((const float4*)gamma)[tid];
    const float4 be = ((const float4*)beta)[tid];
    float o0 = (v.x - mu) * inv * g.x + be.x;
    float o1 = (v.y - mu) * inv * g.y + be.y;
    float o2 = (v.z - mu) * inv * g.z + be.z;
    float o3 = (v.w - mu) * inv * g.w + be.w;
    size_t o = (size_t)t * DIM + tid * 4;
    uint2 h = make_uint2(hi2(o0, o1), hi2(o2, o3));
    uint2 l = make_uint2(lo2(o0, o1), lo2(o2, o3));
    *(uint2*)&xh[o] = h;
    *(uint2*)&xl[o] = l;
}

// ---------------- transpose + split weights ----------------------------------
__global__ void transpose_split_kernel(const float* __restrict__ w,
                                       bf16* __restrict__ wh,
                                       bf16* __restrict__ wl, int K, int N) {
    __shared__ float tile[32][33];
    int n0 = blockIdx.x * 32, k0 = blockIdx.y * 32;
    int tx = threadIdx.x, ty = threadIdx.y;  // 32 x 8
#pragma unroll
    for (int i = 0; i < 32; i += 8)
        tile[ty + i][tx] = w[(size_t)(k0 + ty + i) * N + n0 + tx];
    __syncthreads();
#pragma unroll
    for (int i = 0; i < 32; i += 8) {
        float v = tile[tx][ty + i];
        bf16 h, l; split2(v, h, l);
        size_t o = (size_t)(n0 + ty + i) * K + k0 + tx;
        wh[o] = h; wl[o] = l;
    }
}

// ---------------- bf16x3 GEMM (cp.async 3-stage + ldmatrix) ------------------
// C[M,N] = A[M,K] @ Bt[N,K]^T (+bias). BM=BN=128, BK=32, 8 warps (4x2).
// smem stage: Ah,Al,Bh,Bl each 128 rows x 40 bf16 (80B stride) = 10240B.
template <bool HAS_BIAS>
__global__ __launch_bounds__(256)
void gemm_kernel(const bf16* __restrict__ Agh, const bf16* __restrict__ Agl,
                 const bf16* __restrict__ Bgh, const bf16* __restrict__ Bgl,
                 const float* __restrict__ bias, float* __restrict__ C,
                 int M, int N, int K) {
    extern __shared__ __align__(16) unsigned char sm[];
    uint32_t smb = (uint32_t)__cvta_generic_to_shared(sm);
    const int tid = threadIdx.x;
    const int wid = tid >> 5, lane = tid & 31;
    const int wm = wid >> 1, wn = wid & 1;
    const int g = lane >> 2, t2 = (lane & 3) * 2;
    const int within = lane & 7, grp = lane >> 3;
    const int m0 = blockIdx.y * 128, n0 = blockIdx.x * 128;
    const int r = tid >> 1, c2 = (tid & 1) * 2;
    const int NIT = K >> 5;

    float acc[2][8][4];
#pragma unroll
    for (int i = 0; i < 2; i++)
#pragma unroll
        for (int j = 0; j < 8; j++)
#pragma unroll
            for (int k = 0; k < 4; k++) acc[i][j][k] = 0.f;

    auto issue = [&](int it) {
        int k0 = it << 5;
        uint32_t sb = smb + (uint32_t)(it % 3) * 40960u;
        uint32_t off = (uint32_t)r * 80u + (uint32_t)c2 * 16u;
        const bf16* p = Agh + (size_t)(m0 + r) * K + k0 + c2 * 8;
        cpa16(sb + off, p);            cpa16(sb + off + 16, p + 8);
        p = Agl + (size_t)(m0 + r) * K + k0 + c2 * 8;
        cpa16(sb + 10240 + off, p);    cpa16(sb + 10240 + off + 16, p + 8);
        p = Bgh + (size_t)(n0 + r) * K + k0 + c2 * 8;
        cpa16(sb + 20480 + off, p);    cpa16(sb + 20480 + off + 16, p + 8);
        p = Bgl + (size_t)(n0 + r) * K + k0 + c2 * 8;
        cpa16(sb + 30720 + off, p);    cpa16(sb + 30720 + off + 16, p + 8);
        CP_COMMIT;
    };
    issue(0); issue(1);

    for (int it = 0; it < NIT; it++) {
        CP_WAIT1;
        __syncthreads();
        if (it + 2 < NIT) issue(it + 2);
        uint32_t sb = smb + (uint32_t)(it % 3) * 40960u;
#pragma unroll
        for (int kk8 = 0; kk8 < 4; kk8 += 2) {  // seg base for kk=0,16
            uint32_t aH[2][4], aL[2][4], bH[8][2], bL[8][2];
#pragma unroll
            for (int mt = 0; mt < 2; mt++) {
                uint32_t ra = (uint32_t)(wm * 32 + mt * 16 + within + (grp & 1) * 8);
                uint32_t sa = (uint32_t)(kk8 + (grp >> 1));
                ldsm4(aH[mt], sb + ra * 80u + sa * 16u);
                ldsm4(aL[mt], sb + 10240u + ra * 80u + sa * 16u);
            }
#pragma unroll
            for (int ntp = 0; ntp < 4; ntp++) {
                uint32_t rb = (uint32_t)(wn * 64 + ntp * 16 + within + (grp >> 1) * 8);
                uint32_t sg = (uint32_t)(kk8 + (grp & 1));
                uint32_t t4[4];
                ldsm4(t4, sb + 20480u + rb * 80u + sg * 16u);
                bH[2 * ntp][0] = t4[0]; bH[2 * ntp][1] = t4[1];
                bH[2 * ntp + 1][0] = t4[2]; bH[2 * ntp + 1][1] = t4[3];
                ldsm4(t4, sb + 30720u + rb * 80u + sg * 16u);
                bL[2 * ntp][0] = t4[0]; bL[2 * ntp][1] = t4[1];
                bL[2 * ntp + 1][0] = t4[2]; bL[2 * ntp + 1][1] = t4[3];
            }
#pragma unroll
            for (int mt = 0; mt < 2; mt++)
#pragma unroll
                for (int nt = 0; nt < 8; nt++) {
                    mma16816(acc[mt][nt], aH[mt], bH[nt]);
                    mma16816(acc[mt][nt], aH[mt], bL[nt]);
                    mma16816(acc[mt][nt], aL[mt], bH[nt]);
                }
        }
    }

#pragma unroll
    for (int mt = 0; mt < 2; mt++) {
#pragma unroll
        for (int nt = 0; nt < 8; nt++) {
            int row = m0 + wm * 32 + mt * 16 + g;
            int col = n0 + wn * 64 + nt * 8 + t2;
            float b0 = 0.f, b1 = 0.f;
            if (HAS_BIAS) { b0 = bias[col]; b1 = bias[col + 1]; }
            float2 v0 = make_float2(acc[mt][nt][0] + b0, acc[mt][nt][1] + b1);
            float2 v1 = make_float2(acc[mt][nt][2] + b0, acc[mt][nt][3] + b1);
            *(float2*)&C[(size_t)row * N + col] = v0;
            *(float2*)&C[(size_t)(row + 8) * N + col] = v1;
        }
    }
}

// ---------------- RoPE + split + head-major relayout -------------------------
__global__ void rope_convert_kernel(const float* __restrict__ qkv,
                                    bf16* __restrict__ qh, bf16* __restrict__ ql,
                                    bf16* __restrict__ kh, bf16* __restrict__ kl,
                                    bf16* __restrict__ vh, bf16* __restrict__ vl) {
    int idx = blockIdx.x * 256 + threadIdx.x;
    if (idx >= T * HEADS * 32) return;
    int i = idx & 31;
    int h = (idx >> 5) & (HEADS - 1);
    int t = idx >> 9;
    int pos = t & (SEQ - 1);
    int b = t >> 11;
    float inv = exp2f(-(float)i * (13.287712379549449f / 32.f));
    float ang = (float)pos * inv;
    float sn, cs;
    sincosf(ang, &sn, &cs);
    size_t base = (size_t)t * (3 * INNER) + h * DH + 2 * i;
    float qe = qkv[base],        qo = qkv[base + 1];
    float ke = qkv[base + INNER], ko = qkv[base + INNER + 1];
    float v0 = qkv[base + 2 * INNER], v1 = qkv[base + 2 * INNER + 1];
    float q0 = qe * cs - qo * sn, q1 = qe * sn + qo * cs;
    float k0 = ke * cs - ko * sn, k1 = ke * sn + ko * cs;
    size_t o = (((size_t)(b * HEADS + h)) * SEQ + pos) * DH + 2 * i;
    *(uint32_t*)&qh[o] = hi2(q0, q1); *(uint32_t*)&ql[o] = lo2(q0, q1);
    *(uint32_t*)&kh[o] = hi2(k0, k1); *(uint32_t*)&kl[o] = lo2(k0, k1);
    *(uint32_t*)&vh[o] = hi2(v0, v1); *(uint32_t*)&vl[o] = lo2(v0, v1);
}

// ---------------- Flash attention (bf16x3, cp.async + ldmatrix) --------------
// 128 q-rows/CTA, 8 warps (16 rows each), KV chunks of 64, 3-stage KV ring.
// smem (bytes): Qh@0, Ql@18432 (128x72 bf16, 144B stride);
//   KV stage s @ 36864+s*36864: Kh+0, Kl+9216, Vh+18432, Vl+27648 (64x72 each).
__global__ __launch_bounds__(256)
void attn_kernel(const bf16* __restrict__ qgh, const bf16* __restrict__ qgl,
                 const bf16* __restrict__ kgh, const bf16* __restrict__ kgl,
                 const bf16* __restrict__ vgh, const bf16* __restrict__ vgl,
                 bf16* __restrict__ oh, bf16* __restrict__ ol) {
    extern __shared__ __align__(16) unsigned char sm[];
    uint32_t smb = (uint32_t)__cvta_generic_to_shared(sm);
    const uint32_t QH = 0, QL = 18432, KV0 = 36864, KVS = 36864;

    const int tid = threadIdx.x, wid = tid >> 5, lane = tid & 31;
    const int g = lane >> 2, t2 = (lane & 3) * 2;
    const int within = lane & 7, grp = lane >> 3;
    const int b = blockIdx.z, h = blockIdx.y;
    const int q0 = blockIdx.x * 128;
    const size_t hb = (size_t)(b * HEADS + h) * SEQ * DH;

    // Q tile via cp.async (one group)
    {
        int rq = tid >> 1, c4 = (tid & 1) * 4;
        uint32_t d = smb + QH + (uint32_t)rq * 144u + (uint32_t)c4 * 16u;
        const bf16* p = qgh + hb + (size_t)(q0 + rq) * DH + c4 * 8;
        cpa16(d, p); cpa16(d + 16, p + 8); cpa16(d + 32, p + 16); cpa16(d + 48, p + 24);
        d = smb + QL + (uint32_t)rq * 144u + (uint32_t)c4 * 16u;
        p = qgl + hb + (size_t)(q0 + rq) * DH + c4 * 8;
        cpa16(d, p); cpa16(d + 16, p + 8); cpa16(d + 32, p + 16); cpa16(d + 48, p + 24);
        CP_COMMIT;
    }
    const int rkv = tid >> 2, ckv = (tid & 3) * 2;
    auto issueKV = [&](int j) {
        uint32_t sb = smb + KV0 + (uint32_t)(j % 3) * KVS;
        uint32_t off = (uint32_t)rkv * 144u + (uint32_t)ckv * 16u;
        const bf16* p = kgh + hb + (size_t)(j * 64 + rkv) * DH + ckv * 8;
        cpa16(sb + off, p);            cpa16(sb + off + 16, p + 8);
        p = kgl + hb + (size_t)(j * 64 + rkv) * DH + ckv * 8;
        cpa16(sb + 9216 + off, p);     cpa16(sb + 9216 + off + 16, p + 8);
        p = vgh + hb + (size_t)(j * 64 + rkv) * DH + ckv * 8;
        cpa16(sb + 18432 + off, p);    cpa16(sb + 18432 + off + 16, p + 8);
        p = vgl + hb + (size_t)(j * 64 + rkv) * DH + ckv * 8;
        cpa16(sb + 27648 + off, p);    cpa16(sb + 27648 + off + 16, p + 8);
        CP_COMMIT;
    };
    issueKV(0); issueKV(1);

    CP_WAIT2;            // Q group done (2 KV groups may remain in flight)
    __syncthreads();

    // hoist Q fragments to registers (reused for all 32 KV chunks)
    uint32_t qH[4][4], qL[4][4];
    const int qr = wid * 16;
#pragma unroll
    for (int kk4 = 0; kk4 < 4; kk4++) {
        uint32_t ra = (uint32_t)(qr + within + (grp & 1) * 8);
        uint32_t sa = (uint32_t)(kk4 * 2 + (grp >> 1));
        ldsm4(qH[kk4], smb + QH + ra * 144u + sa * 16u);
        ldsm4(qL[kk4], smb + QL + ra * 144u + sa * 16u);
    }

    float m0v = -1e30f, m1v = -1e30f, l0v = 0.f, l1v = 0.f;
    float oacc[8][4];
#pragma unroll
    for (int i = 0; i < 8; i++)
#pragma unroll
        for (int j = 0; j < 4; j++) oacc[i][j] = 0.f;

    for (int j = 0; j < SEQ / 64; j++) {
        CP_WAIT1;
        __syncthreads();
        if (j + 2 < SEQ / 64) issueKV(j + 2);
        uint32_t sb = smb + KV0 + (uint32_t)(j % 3) * KVS;

        // ---- S = Q K^T ----
        float sacc[8][4];
#pragma unroll
        for (int i = 0; i < 8; i++)
#pragma unroll
            for (int jj = 0; jj < 4; jj++) sacc[i][jj] = 0.f;
#pragma unroll
        for (int kk4 = 0; kk4 < 4; kk4++) {
#pragma unroll
            for (int ntp = 0; ntp < 4; ntp++) {
                uint32_t rb = (uint32_t)(ntp * 16 + within + (grp >> 1) * 8);
                uint32_t sg = (uint32_t)(kk4 * 2 + (grp & 1));
                uint32_t t4[4], u4[4];
                ldsm4(t4, sb + rb * 144u + sg * 16u);           // Kh
                ldsm4(u4, sb + 9216u + rb * 144u + sg * 16u);   // Kl
                uint32_t bh0[2] = {t4[0], t4[1]}, bh1[2] = {t4[2], t4[3]};
                uint32_t bl0[2] = {u4[0], u4[1]}, bl1[2] = {u4[2], u4[3]};
                mma16816(sacc[2 * ntp],     qH[kk4], bh0);
                mma16816(sacc[2 * ntp],     qH[kk4], bl0);
                mma16816(sacc[2 * ntp],     qL[kk4], bh0);
                mma16816(sacc[2 * ntp + 1], qH[kk4], bh1);
                mma16816(sacc[2 * ntp + 1], qH[kk4], bl1);
                mma16816(sacc[2 * ntp + 1], qL[kk4], bh1);
            }
        }

        // ---- online softmax ----
        const float scale = 0.125f;
        float mx0 = -1e30f, mx1 = -1e30f;
#pragma unroll
        for (int nt = 0; nt < 8; nt++) {
#pragma unroll
            for (int jj = 0; jj < 4; jj++) sacc[nt][jj] *= scale;
            mx0 = fmaxf(mx0, fmaxf(sacc[nt][0], sacc[nt][1]));
            mx1 = fmaxf(mx1, fmaxf(sacc[nt][2], sacc[nt][3]));
        }
#pragma unroll
        for (int o = 1; o <= 2; o <<= 1) {
            mx0 = fmaxf(mx0, __shfl_xor_sync(0xffffffffu, mx0, o));
            mx1 = fmaxf(mx1, __shfl_xor_sync(0xffffffffu, mx1, o));
        }
        float mn0 = fmaxf(m0v, mx0), mn1 = fmaxf(m1v, mx1);
        float al0 = __expf(m0v - mn0), al1 = __expf(m1v - mn1);
        float sum0 = 0.f, sum1 = 0.f;
#pragma unroll
        for (int nt = 0; nt < 8; nt++) {
            sacc[nt][0] = __expf(sacc[nt][0] - mn0);
            sacc[nt][1] = __expf(sacc[nt][1] - mn0);
            sacc[nt][2] = __expf(sacc[nt][2] - mn1);
            sacc[nt][3] = __expf(sacc[nt][3] - mn1);
            sum0 += sacc[nt][0] + sacc[nt][1];
            sum1 += sacc[nt][2] + sacc[nt][3];
        }
#pragma unroll
        for (int o = 1; o <= 2; o <<= 1) {
            sum0 += __shfl_xor_sync(0xffffffffu, sum0, o);
            sum1 += __shfl_xor_sync(0xffffffffu, sum1, o);
        }
        l0v = l0v * al0 + sum0; m0v = mn0;
        l1v = l1v * al1 + sum1; m1v = mn1;
#pragma unroll
        for (int nt = 0; nt < 8; nt++) {
            oacc[nt][0] *= al0; oacc[nt][1] *= al0;
            oacc[nt][2] *= al1; oacc[nt][3] *= al1;
        }

        // ---- O += P V (V via ldmatrix.trans) ----
#pragma unroll
        for (int kt = 0; kt < 4; kt++) {
            uint32_t pH[4], pL[4];
            pH[0] = hi2(sacc[2 * kt][0],     sacc[2 * kt][1]);
            pH[1] = hi2(sacc[2 * kt][2],     sacc[2 * kt][3]);
            pH[2] = hi2(sacc[2 * kt + 1][0], sacc[2 * kt + 1][1]);
            pH[3] = hi2(sacc[2 * kt + 1][2], sacc[2 * kt + 1][3]);
            pL[0] = lo2(sacc[2 * kt][0],     sacc[2 * kt][1]);
            pL[1] = lo2(sacc[2 * kt][2],     sacc[2 * kt][3]);
            pL[2] = lo2(sacc[2 * kt + 1][0], sacc[2 * kt + 1][1]);
            pL[3] = lo2(sacc[2 * kt + 1][2], sacc[2 * kt + 1][3]);
#pragma unroll
            for (int ntp = 0; ntp < 4; ntp++) {
                uint32_t tok = (uint32_t)(kt * 16 + within + (grp & 1) * 8);
                uint32_t sg  = (uint32_t)(ntp * 2 + (grp >> 1));
                uint32_t t4[4], u4[4];
                ldsm4t(t4, sb + 18432u + tok * 144u + sg * 16u);  // Vh
                ldsm4t(u4, sb + 27648u + tok * 144u + sg * 16u);  // Vl
                uint32_t bh0[2] = {t4[0], t4[1]}, bh1[2] = {t4[2], t4[3]};
                uint32_t bl0[2] = {u4[0], u4[1]}, bl1[2] = {u4[2], u4[3]};
                mma16816(oacc[2 * ntp],     pH, bh0);
                mma16816(oacc[2 * ntp],     pH, bl0);
                mma16816(oacc[2 * ntp],     pL, bh0);
                mma16816(oacc[2 * ntp + 1], pH, bh1);
                mma16816(oacc[2 * ntp + 1], pH, bl1);
                mma16816(oacc[2 * ntp + 1], pL, bh1);
            }
        }
    }

    // ---- epilogue ----
    float i0 = 1.f / l0v, i1 = 1.f / l1v;
#pragma unroll
    for (int nt = 0; nt < 8; nt++) {
        int row = q0 + qr + g;
        int col = h * DH + nt * 8 + t2;
        size_t ob = (size_t)(b * SEQ + row) * INNER + col;
        float a0 = oacc[nt][0] * i0, a1 = oacc[nt][1] * i0;
        float a2 = oacc[nt][2] * i1, a3 = oacc[nt][3] * i1;
        *(uint32_t*)&oh[ob] = hi2(a0, a1);
        *(uint32_t*)&ol[ob] = lo2(a0, a1);
        size_t ob2 = ob + (size_t)8 * INNER;
        *(uint32_t*)&oh[ob2] = hi2(a2, a3);
        *(uint32_t*)&ol[ob2] = lo2(a2, a3);
    }
}

// ---------------- launch -----------------------------------------------------
extern "C" void kernel_launch(void* const* d_in, const int* in_sizes, int n_in,
                              void* d_out, int out_size) {
    const float* x     = (const float*)d_in[0];
    const float* gamma = (const float*)d_in[1];
    const float* beta  = (const float*)d_in[2];
    const float* w_qkv = (const float*)d_in[3];
    const float* w_out = (const float*)d_in[4];
    const float* b_out = (const float*)d_in[5];
    float* out = (float*)d_out;

    bf16 *xnh, *xnl, *wqh, *wql, *woh, *wol;
    bf16 *qh, *ql, *kh, *kl, *vh, *vl, *ah, *al;
    float* qkv;
    cudaGetSymbolAddress((void**)&xnh, g_xn_hi);
    cudaGetSymbolAddress((void**)&xnl, g_xn_lo);
    cudaGetSymbolAddress((void**)&wqh, g_wqt_hi);
    cudaGetSymbolAddress((void**)&wql, g_wqt_lo);
    cudaGetSymbolAddress((void**)&woh, g_wot_hi);
    cudaGetSymbolAddress((void**)&wol, g_wot_lo);
    cudaGetSymbolAddress((void**)&qkv, g_qkv);
    cudaGetSymbolAddress((void**)&qh, g_q_hi);
    cudaGetSymbolAddress((void**)&ql, g_q_lo);
    cudaGetSymbolAddress((void**)&kh, g_k_hi);
    cudaGetSymbolAddress((void**)&kl, g_k_lo);
    cudaGetSymbolAddress((void**)&vh, g_v_hi);
    cudaGetSymbolAddress((void**)&vl, g_v_lo);
    cudaGetSymbolAddress((void**)&ah, g_att_hi);
    cudaGetSymbolAddress((void**)&al, g_att_lo);

    const int GEMM_SMEM = 122880;   // 3 stages x 4 arrays x 10240B
    const int ATTN_SMEM = 147456;   // Q 2x18432 + 3 KV stages x 36864
    cudaFuncSetAttribute(gemm_kernel<false>,
                         cudaFuncAttributeMaxDynamicSharedMemorySize, GEMM_SMEM);
    cudaFuncSetAttribute(gemm_kernel<true>,
                         cudaFuncAttributeMaxDynamicSharedMemorySize, GEMM_SMEM);
    cudaFuncSetAttribute(attn_kernel,
                         cudaFuncAttributeMaxDynamicSharedMemorySize, ATTN_SMEM);

    // 1) LayerNorm -> split bf16
    ln_split_kernel<<<T, 256>>>(x, gamma, beta, xnh, xnl);
    // 2) weight transposes + splits
    transpose_split_kernel<<<dim3(3 * INNER / 32, DIM / 32), dim3(32, 8)>>>(
        w_qkv, wqh, wql, DIM, 3 * INNER);
    transpose_split_kernel<<<dim3(DIM / 32, INNER / 32), dim3(32, 8)>>>(
        w_out, woh, wol, INNER, DIM);
    // 3) QKV GEMM (fp32 out)
    gemm_kernel<false><<<dim3(3 * INNER / 128, T / 128), 256, GEMM_SMEM>>>(
        xnh, xnl, wqh, wql, nullptr, qkv, T, 3 * INNER, DIM);
    // 4) RoPE + split + relayout
    rope_convert_kernel<<<(T * HEADS * 32 + 255) / 256, 256>>>(
        qkv, qh, ql, kh, kl, vh, vl);
    // 5) Attention (tensor-core bf16x3)
    attn_kernel<<<dim3(SEQ / 128, HEADS, BATCH), 256, ATTN_SMEM>>>(
        qh, ql, kh, kl, vh, vl, ah, al);
    // 6) Output projection + bias
    gemm_kernel<true><<<dim3(DIM / 128, T / 128), 256, GEMM_SMEM>>>(
        ah, al, woh, wol, b_out, out, T, DIM, INNER);
}

// round 10
// speedup vs baseline: 3.2913x; 1.2165x over previous
#include <cuda_runtime.h>
#include <cuda_bf16.h>
#include <math.h>
#include <stdint.h>

#define DIM   1024
#define HEADS 16
#define DH    64
#define INNER 1024
#define BATCH 4
#define SEQ   2048
#define T     (BATCH * SEQ)   // 8192 tokens

typedef __nv_bfloat16 bf16;

// ---------------- scratch (device globals) ----------------------------------
__device__ bf16  g_xn_hi[T * DIM],        g_xn_lo[T * DIM];
__device__ bf16  g_wqt_hi[3 * INNER * DIM], g_wqt_lo[3 * INNER * DIM]; // [N][K]
__device__ bf16  g_wot_hi[DIM * INNER],   g_wot_lo[DIM * INNER];       // [N][K]
__device__ float g_qkv[T * 3 * INNER];
__device__ bf16  g_q_hi[T * INNER], g_q_lo[T * INNER];  // [b][h][n][d]
__device__ bf16  g_k_hi[T * INNER], g_k_lo[T * INNER];
__device__ bf16  g_v_hi[T * INNER], g_v_lo[T * INNER];
__device__ bf16  g_att_hi[T * INNER], g_att_lo[T * INNER]; // [t][h*64+d]

// ---------------- helpers ----------------------------------------------------
__device__ __forceinline__ uint32_t pack2(bf16 a, bf16 b) {
    return (uint32_t)__bfloat16_as_ushort(a) |
           ((uint32_t)__bfloat16_as_ushort(b) << 16);
}
__device__ __forceinline__ void split2(float x, bf16& h, bf16& l) {
    h = __float2bfloat16(x);
    l = __float2bfloat16(x - __bfloat162float(h));
}
__device__ __forceinline__ uint32_t hi2(float a, float b) {
    return pack2(__float2bfloat16(a), __float2bfloat16(b));
}
__device__ __forceinline__ uint32_t lo2(float a, float b) {
    bf16 ha = __float2bfloat16(a), hb = __float2bfloat16(b);
    return pack2(__float2bfloat16(a - __bfloat162float(ha)),
                 __float2bfloat16(b - __bfloat162float(hb)));
}
__device__ __forceinline__ void mma16816(float c[4], const uint32_t a[4],
                                         const uint32_t b[2]) {
    asm volatile(
        "mma.sync.aligned.m16n8k16.row.col.f32.bf16.bf16.f32 "
        "{%0,%1,%2,%3}, {%4,%5,%6,%7}, {%8,%9}, {%0,%1,%2,%3};\n"
        : "+f"(c[0]), "+f"(c[1]), "+f"(c[2]), "+f"(c[3])
        : "r"(a[0]), "r"(a[1]), "r"(a[2]), "r"(a[3]), "r"(b[0]), "r"(b[1]));
}
__device__ __forceinline__ void ldsm4(uint32_t r[4], uint32_t addr) {
    asm volatile("ldmatrix.sync.aligned.m8n8.x4.shared.b16 {%0,%1,%2,%3}, [%4];"
        : "=r"(r[0]), "=r"(r[1]), "=r"(r[2]), "=r"(r[3]) : "r"(addr));
}
__device__ __forceinline__ void ldsm4t(uint32_t r[4], uint32_t addr) {
    asm volatile("ldmatrix.sync.aligned.m8n8.x4.trans.shared.b16 {%0,%1,%2,%3}, [%4];"
        : "=r"(r[0]), "=r"(r[1]), "=r"(r[2]), "=r"(r[3]) : "r"(addr));
}
__device__ __forceinline__ void cpa16(uint32_t dst, const void* src) {
    asm volatile("cp.async.cg.shared.global [%0], [%1], 16;" :: "r"(dst), "l"(src));
}
#define CP_COMMIT asm volatile("cp.async.commit_group;" ::: "memory")
#define CP_WAIT1  asm volatile("cp.async.wait_group 1;" ::: "memory")
#define CP_WAIT2  asm volatile("cp.async.wait_group 2;" ::: "memory")

// swizzled offsets: 64B rows (4 x 16B chunks), chunk' = c ^ ((r>>1)&3)
__device__ __forceinline__ uint32_t sw64(uint32_t row, uint32_t chunk) {
    return row * 64u + ((chunk ^ ((row >> 1) & 3u)) * 16u);
}
// 128B rows (8 x 16B chunks), chunk' = c ^ (r&7)
__device__ __forceinline__ uint32_t sw128(uint32_t row, uint32_t chunk) {
    return row * 128u + ((chunk ^ (row & 7u)) * 16u);
}

// ---------------- LayerNorm -> split bf16 ------------------------------------
__global__ void ln_split_kernel(const float* __restrict__ x,
                                const float* __restrict__ gamma,
                                const float* __restrict__ beta,
                                bf16* __restrict__ xh, bf16* __restrict__ xl) {
    int t = blockIdx.x, tid = threadIdx.x;
    const float4 v = ((const float4*)(x + (size_t)t * DIM))[tid];
    float s  = v.x + v.y + v.z + v.w;
    float ss = v.x * v.x + v.y * v.y + v.z * v.z + v.w * v.w;
#pragma unroll
    for (int o = 16; o; o >>= 1) {
        s  += __shfl_xor_sync(0xffffffffu, s,  o);
        ss += __shfl_xor_sync(0xffffffffu, ss, o);
    }
    __shared__ float rs[8], rq[8], stats[2];
    if ((tid & 31) == 0) { rs[tid >> 5] = s; rq[tid >> 5] = ss; }
    __syncthreads();
    if (tid == 0) {
        float a = 0.f, b2 = 0.f;
#pragma unroll
        for (int i = 0; i < 8; i++) { a += rs[i]; b2 += rq[i]; }
        float mu  = a * (1.f / DIM);
        float var = b2 * (1.f / DIM) - mu * mu;
        stats[0] = mu; stats[1] = rsqrtf(var + 1e-5f);
    }
    __syncthreads();
    float mu = stats[0], inv = stats[1];
    const float4 g  = ((const float4*)gamma)[tid];
    const float4 be = ((const float4*)beta)[tid];
    float o0 = (v.x - mu) * inv * g.x + be.x;
    float o1 = (v.y - mu) * inv * g.y + be.y;
    float o2 = (v.z - mu) * inv * g.z + be.z;
    float o3 = (v.w - mu) * inv * g.w + be.w;
    size_t o = (size_t)t * DIM + tid * 4;
    uint2 h = make_uint2(hi2(o0, o1), hi2(o2, o3));
    uint2 l = make_uint2(lo2(o0, o1), lo2(o2, o3));
    *(uint2*)&xh[o] = h;
    *(uint2*)&xl[o] = l;
}

// ---------------- transpose + split weights ----------------------------------
__global__ void transpose_split_kernel(const float* __restrict__ w,
                                       bf16* __restrict__ wh,
                                       bf16* __restrict__ wl, int K, int N) {
    __shared__ float tile[32][33];
    int n0 = blockIdx.x * 32, k0 = blockIdx.y * 32;
    int tx = threadIdx.x, ty = threadIdx.y;  // 32 x 8
#pragma unroll
    for (int i = 0; i < 32; i += 8)
        tile[ty + i][tx] = w[(size_t)(k0 + ty + i) * N + n0 + tx];
    __syncthreads();
#pragma unroll
    for (int i = 0; i < 32; i += 8) {
        float v = tile[tx][ty + i];
        bf16 h, l; split2(v, h, l);
        size_t o = (size_t)(n0 + ty + i) * K + k0 + tx;
        wh[o] = h; wl[o] = l;
    }
}

// ---------------- bf16x3 GEMM (cp.async 3-stage, swizzled, 2 CTA/SM) ---------
// C[M,N] = A[M,K] @ Bt[N,K]^T (+bias). BM=BN=128, BK=32, 8 warps (4x2).
// Stage 32768B: Ah@0, Al@8192, Bh@16384, Bl@24576; each 128 rows x 64B swz.
template <bool HAS_BIAS>
__global__ __launch_bounds__(256, 2)
void gemm_kernel(const bf16* __restrict__ Agh, const bf16* __restrict__ Agl,
                 const bf16* __restrict__ Bgh, const bf16* __restrict__ Bgl,
                 const float* __restrict__ bias, float* __restrict__ C,
                 int M, int N, int K) {
    extern __shared__ __align__(16) unsigned char sm[];
    uint32_t smb = (uint32_t)__cvta_generic_to_shared(sm);
    const int tid = threadIdx.x;
    const int wid = tid >> 5, lane = tid & 31;
    const int wm = wid >> 1, wn = wid & 1;
    const int g = lane >> 2, t2 = (lane & 3) * 2;
    const int within = lane & 7, grp = lane >> 3;
    const int m0 = blockIdx.y * 128, n0 = blockIdx.x * 128;
    const int r = tid >> 1, c2 = (tid & 1) * 2;
    const int NIT = K >> 5;

    float acc[2][8][4];
#pragma unroll
    for (int i = 0; i < 2; i++)
#pragma unroll
        for (int j = 0; j < 8; j++)
#pragma unroll
            for (int k = 0; k < 4; k++) acc[i][j][k] = 0.f;

    auto issue = [&](int it) {
        int k0 = it << 5;
        uint32_t sb = smb + (uint32_t)(it % 3) * 32768u;
        uint32_t o0 = sw64((uint32_t)r, (uint32_t)c2);
        uint32_t o1 = sw64((uint32_t)r, (uint32_t)c2 + 1);
        const bf16* p = Agh + (size_t)(m0 + r) * K + k0 + c2 * 8;
        cpa16(sb + o0, p);             cpa16(sb + o1, p + 8);
        p = Agl + (size_t)(m0 + r) * K + k0 + c2 * 8;
        cpa16(sb + 8192 + o0, p);      cpa16(sb + 8192 + o1, p + 8);
        p = Bgh + (size_t)(n0 + r) * K + k0 + c2 * 8;
        cpa16(sb + 16384 + o0, p);     cpa16(sb + 16384 + o1, p + 8);
        p = Bgl + (size_t)(n0 + r) * K + k0 + c2 * 8;
        cpa16(sb + 24576 + o0, p);     cpa16(sb + 24576 + o1, p + 8);
        CP_COMMIT;
    };
    issue(0); issue(1);

    for (int it = 0; it < NIT; it++) {
        CP_WAIT1;
        __syncthreads();
        if (it + 2 < NIT) issue(it + 2);
        uint32_t sb = smb + (uint32_t)(it % 3) * 32768u;
#pragma unroll
        for (int kk8 = 0; kk8 < 4; kk8 += 2) {  // chunk base for kk=0,16
            uint32_t aH[2][4], aL[2][4], bH[8][2], bL[8][2];
#pragma unroll
            for (int mt = 0; mt < 2; mt++) {
                uint32_t ra = (uint32_t)(wm * 32 + mt * 16 + within + (grp & 1) * 8);
                uint32_t sa = (uint32_t)(kk8 + (grp >> 1));
                ldsm4(aH[mt], sb + sw64(ra, sa));
                ldsm4(aL[mt], sb + 8192u + sw64(ra, sa));
            }
#pragma unroll
            for (int ntp = 0; ntp < 4; ntp++) {
                uint32_t rb = (uint32_t)(wn * 64 + ntp * 16 + within + (grp >> 1) * 8);
                uint32_t sg = (uint32_t)(kk8 + (grp & 1));
                uint32_t t4[4];
                ldsm4(t4, sb + 16384u + sw64(rb, sg));
                bH[2 * ntp][0] = t4[0]; bH[2 * ntp][1] = t4[1];
                bH[2 * ntp + 1][0] = t4[2]; bH[2 * ntp + 1][1] = t4[3];
                ldsm4(t4, sb + 24576u + sw64(rb, sg));
                bL[2 * ntp][0] = t4[0]; bL[2 * ntp][1] = t4[1];
                bL[2 * ntp + 1][0] = t4[2]; bL[2 * ntp + 1][1] = t4[3];
            }
#pragma unroll
            for (int mt = 0; mt < 2; mt++)
#pragma unroll
                for (int nt = 0; nt < 8; nt++) {
                    mma16816(acc[mt][nt], aH[mt], bH[nt]);
                    mma16816(acc[mt][nt], aH[mt], bL[nt]);
                    mma16816(acc[mt][nt], aL[mt], bH[nt]);
                }
        }
    }

#pragma unroll
    for (int mt = 0; mt < 2; mt++) {
#pragma unroll
        for (int nt = 0; nt < 8; nt++) {
            int row = m0 + wm * 32 + mt * 16 + g;
            int col = n0 + wn * 64 + nt * 8 + t2;
            float b0 = 0.f, b1 = 0.f;
            if (HAS_BIAS) { b0 = bias[col]; b1 = bias[col + 1]; }
            float2 v0 = make_float2(acc[mt][nt][0] + b0, acc[mt][nt][1] + b1);
            float2 v1 = make_float2(acc[mt][nt][2] + b0, acc[mt][nt][3] + b1);
            *(float2*)&C[(size_t)row * N + col] = v0;
            *(float2*)&C[(size_t)(row + 8) * N + col] = v1;
        }
    }
}

// ---------------- RoPE + split + head-major relayout -------------------------
__global__ void rope_convert_kernel(const float* __restrict__ qkv,
                                    bf16* __restrict__ qh, bf16* __restrict__ ql,
                                    bf16* __restrict__ kh, bf16* __restrict__ kl,
                                    bf16* __restrict__ vh, bf16* __restrict__ vl) {
    int idx = blockIdx.x * 256 + threadIdx.x;
    if (idx >= T * HEADS * 32) return;
    int i = idx & 31;
    int h = (idx >> 5) & (HEADS - 1);
    int t = idx >> 9;
    int pos = t & (SEQ - 1);
    int b = t >> 11;
    float inv = exp2f(-(float)i * (13.287712379549449f / 32.f));
    float ang = (float)pos * inv;
    float sn, cs;
    sincosf(ang, &sn, &cs);
    size_t base = (size_t)t * (3 * INNER) + h * DH + 2 * i;
    float qe = qkv[base],        qo = qkv[base + 1];
    float ke = qkv[base + INNER], ko = qkv[base + INNER + 1];
    float v0 = qkv[base + 2 * INNER], v1 = qkv[base + 2 * INNER + 1];
    float q0 = qe * cs - qo * sn, q1 = qe * sn + qo * cs;
    float k0 = ke * cs - ko * sn, k1 = ke * sn + ko * cs;
    size_t o = (((size_t)(b * HEADS + h)) * SEQ + pos) * DH + 2 * i;
    *(uint32_t*)&qh[o] = hi2(q0, q1); *(uint32_t*)&ql[o] = lo2(q0, q1);
    *(uint32_t*)&kh[o] = hi2(k0, k1); *(uint32_t*)&kl[o] = lo2(k0, k1);
    *(uint32_t*)&vh[o] = hi2(v0, v1); *(uint32_t*)&vl[o] = lo2(v0, v1);
}

// ---------------- Flash attention (bf16x3, 2-stage KV ring, 2 CTA/SM) --------
// 128 q-rows/CTA, 8 warps, KV chunks of 64.
// smem: Qh@0 (16384), Ql@16384; KV stage s @ 32768+s*32768:
//   Kh+0, Kl+8192, Vh+16384, Vl+24576  (64 rows x 128B swz each)
__global__ __launch_bounds__(256, 2)
void attn_kernel(const bf16* __restrict__ qgh, const bf16* __restrict__ qgl,
                 const bf16* __restrict__ kgh, const bf16* __restrict__ kgl,
                 const bf16* __restrict__ vgh, const bf16* __restrict__ vgl,
                 bf16* __restrict__ oh, bf16* __restrict__ ol) {
    extern __shared__ __align__(16) unsigned char sm[];
    uint32_t smb = (uint32_t)__cvta_generic_to_shared(sm);
    const uint32_t QH = 0, QL = 16384, KV0 = 32768, KVS = 32768;

    const int tid = threadIdx.x, wid = tid >> 5, lane = tid & 31;
    const int g = lane >> 2, t2 = (lane & 3) * 2;
    const int within = lane & 7, grp = lane >> 3;
    const int b = blockIdx.z, h = blockIdx.y;
    const int q0 = blockIdx.x * 128;
    const size_t hb = (size_t)(b * HEADS + h) * SEQ * DH;

    // Q tile via cp.async (one group)
    {
        int rq = tid >> 1, c4 = (tid & 1) * 4;
        const bf16* ph = qgh + hb + (size_t)(q0 + rq) * DH + c4 * 8;
        const bf16* pl = qgl + hb + (size_t)(q0 + rq) * DH + c4 * 8;
#pragma unroll
        for (int cc = 0; cc < 4; cc++) {
            uint32_t off = sw128((uint32_t)rq, (uint32_t)(c4 + cc));
            cpa16(smb + QH + off, ph + cc * 8);
            cpa16(smb + QL + off, pl + cc * 8);
        }
        CP_COMMIT;
    }
    const int rkv = tid >> 2, ckv = (tid & 3) * 2;
    auto issueKV = [&](int j) {
        uint32_t sb = smb + KV0 + (uint32_t)(j & 1) * KVS;
        uint32_t o0 = sw128((uint32_t)rkv, (uint32_t)ckv);
        uint32_t o1 = sw128((uint32_t)rkv, (uint32_t)ckv + 1);
        const bf16* p = kgh + hb + (size_t)(j * 64 + rkv) * DH + ckv * 8;
        cpa16(sb + o0, p);             cpa16(sb + o1, p + 8);
        p = kgl + hb + (size_t)(j * 64 + rkv) * DH + ckv * 8;
        cpa16(sb + 8192 + o0, p);      cpa16(sb + 8192 + o1, p + 8);
        p = vgh + hb + (size_t)(j * 64 + rkv) * DH + ckv * 8;
        cpa16(sb + 16384 + o0, p);     cpa16(sb + 16384 + o1, p + 8);
        p = vgl + hb + (size_t)(j * 64 + rkv) * DH + ckv * 8;
        cpa16(sb + 24576 + o0, p);     cpa16(sb + 24576 + o1, p + 8);
        CP_COMMIT;
    };
    issueKV(0); issueKV(1);

    CP_WAIT2;            // Q group done (2 KV groups may remain in flight)
    __syncthreads();

    // hoist Q fragments to registers (reused for all 32 KV chunks)
    uint32_t qH[4][4], qL[4][4];
    const int qr = wid * 16;
#pragma unroll
    for (int kk4 = 0; kk4 < 4; kk4++) {
        uint32_t ra = (uint32_t)(qr + within + (grp & 1) * 8);
        uint32_t sa = (uint32_t)(kk4 * 2 + (grp >> 1));
        ldsm4(qH[kk4], smb + QH + sw128(ra, sa));
        ldsm4(qL[kk4], smb + QL + sw128(ra, sa));
    }

    float m0v = -1e30f, m1v = -1e30f, l0v = 0.f, l1v = 0.f;
    float oacc[8][4];
#pragma unroll
    for (int i = 0; i < 8; i++)
#pragma unroll
        for (int j = 0; j < 4; j++) oacc[i][j] = 0.f;

    const int NJ = SEQ / 64;
    for (int j = 0; j < NJ; j++) {
        CP_WAIT1;
        __syncthreads();
        uint32_t sb = smb + KV0 + (uint32_t)(j & 1) * KVS;

        // ---- S = Q K^T ----
        float sacc[8][4];
#pragma unroll
        for (int i = 0; i < 8; i++)
#pragma unroll
            for (int jj = 0; jj < 4; jj++) sacc[i][jj] = 0.f;
#pragma unroll
        for (int kk4 = 0; kk4 < 4; kk4++) {
#pragma unroll
            for (int ntp = 0; ntp < 4; ntp++) {
                uint32_t rb = (uint32_t)(ntp * 16 + within + (grp >> 1) * 8);
                uint32_t sg = (uint32_t)(kk4 * 2 + (grp & 1));
                uint32_t t4[4], u4[4];
                ldsm4(t4, sb + sw128(rb, sg));           // Kh
                ldsm4(u4, sb + 8192u + sw128(rb, sg));   // Kl
                uint32_t bh0[2] = {t4[0], t4[1]}, bh1[2] = {t4[2], t4[3]};
                uint32_t bl0[2] = {u4[0], u4[1]}, bl1[2] = {u4[2], u4[3]};
                mma16816(sacc[2 * ntp],     qH[kk4], bh0);
                mma16816(sacc[2 * ntp],     qH[kk4], bl0);
                mma16816(sacc[2 * ntp],     qL[kk4], bh0);
                mma16816(sacc[2 * ntp + 1], qH[kk4], bh1);
                mma16816(sacc[2 * ntp + 1], qH[kk4], bl1);
                mma16816(sacc[2 * ntp + 1], qL[kk4], bh1);
            }
        }

        // ---- online softmax ----
        const float scale = 0.125f;
        float mx0 = -1e30f, mx1 = -1e30f;
#pragma unroll
        for (int nt = 0; nt < 8; nt++) {
#pragma unroll
            for (int jj = 0; jj < 4; jj++) sacc[nt][jj] *= scale;
            mx0 = fmaxf(mx0, fmaxf(sacc[nt][0], sacc[nt][1]));
            mx1 = fmaxf(mx1, fmaxf(sacc[nt][2], sacc[nt][3]));
        }
#pragma unroll
        for (int o = 1; o <= 2; o <<= 1) {
            mx0 = fmaxf(mx0, __shfl_xor_sync(0xffffffffu, mx0, o));
            mx1 = fmaxf(mx1, __shfl_xor_sync(0xffffffffu, mx1, o));
        }
        float mn0 = fmaxf(m0v, mx0), mn1 = fmaxf(m1v, mx1);
        float al0 = __expf(m0v - mn0), al1 = __expf(m1v - mn1);
        float sum0 = 0.f, sum1 = 0.f;
#pragma unroll
        for (int nt = 0; nt < 8; nt++) {
            sacc[nt][0] = __expf(sacc[nt][0] - mn0);
            sacc[nt][1] = __expf(sacc[nt][1] - mn0);
            sacc[nt][2] = __expf(sacc[nt][2] - mn1);
            sacc[nt][3] = __expf(sacc[nt][3] - mn1);
            sum0 += sacc[nt][0] + sacc[nt][1];
            sum1 += sacc[nt][2] + sacc[nt][3];
        }
#pragma unroll
        for (int o = 1; o <= 2; o <<= 1) {
            sum0 += __shfl_xor_sync(0xffffffffu, sum0, o);
            sum1 += __shfl_xor_sync(0xffffffffu, sum1, o);
        }
        l0v = l0v * al0 + sum0; m0v = mn0;
        l1v = l1v * al1 + sum1; m1v = mn1;
#pragma unroll
        for (int nt = 0; nt < 8; nt++) {
            oacc[nt][0] *= al0; oacc[nt][1] *= al0;
            oacc[nt][2] *= al1; oacc[nt][3] *= al1;
        }

        // ---- O += P V (V via ldmatrix.trans) ----
#pragma unroll
        for (int kt = 0; kt < 4; kt++) {
            uint32_t pH[4], pL[4];
            pH[0] = hi2(sacc[2 * kt][0],     sacc[2 * kt][1]);
            pH[1] = hi2(sacc[2 * kt][2],     sacc[2 * kt][3]);
            pH[2] = hi2(sacc[2 * kt + 1][0], sacc[2 * kt + 1][1]);
            pH[3] = hi2(sacc[2 * kt + 1][2], sacc[2 * kt + 1][3]);
            pL[0] = lo2(sacc[2 * kt][0],     sacc[2 * kt][1]);
            pL[1] = lo2(sacc[2 * kt][2],     sacc[2 * kt][3]);
            pL[2] = lo2(sacc[2 * kt + 1][0], sacc[2 * kt + 1][1]);
            pL[3] = lo2(sacc[2 * kt + 1][2], sacc[2 * kt + 1][3]);
#pragma unroll
            for (int ntp = 0; ntp < 4; ntp++) {
                uint32_t tok = (uint32_t)(kt * 16 + within + (grp & 1) * 8);
                uint32_t sg  = (uint32_t)(ntp * 2 + (grp >> 1));
                uint32_t t4[4], u4[4];
                ldsm4t(t4, sb + 16384u + sw128(tok, sg));  // Vh
                ldsm4t(u4, sb + 24576u + sw128(tok, sg));  // Vl
                uint32_t bh0[2] = {t4[0], t4[1]}, bh1[2] = {t4[2], t4[3]};
                uint32_t bl0[2] = {u4[0], u4[1]}, bl1[2] = {u4[2], u4[3]};
                mma16816(oacc[2 * ntp],     pH, bh0);
                mma16816(oacc[2 * ntp],     pH, bl0);
                mma16816(oacc[2 * ntp],     pL, bh0);
                mma16816(oacc[2 * ntp + 1], pH, bh1);
                mma16816(oacc[2 * ntp + 1], pH, bl1);
                mma16816(oacc[2 * ntp + 1], pL, bh1);
            }
        }

        // all warps done reading stage (j&1) -> safe to refill it
        __syncthreads();
        if (j + 2 < NJ) issueKV(j + 2);
    }

    // ---- epilogue ----
    float i0 = 1.f / l0v, i1 = 1.f / l1v;
#pragma unroll
    for (int nt = 0; nt < 8; nt++) {
        int row = q0 + qr + g;
        int col = h * DH + nt * 8 + t2;
        size_t ob = (size_t)(b * SEQ + row) * INNER + col;
        float a0 = oacc[nt][0] * i0, a1 = oacc[nt][1] * i0;
        float a2 = oacc[nt][2] * i1, a3 = oacc[nt][3] * i1;
        *(uint32_t*)&oh[ob] = hi2(a0, a1);
        *(uint32_t*)&ol[ob] = lo2(a0, a1);
        size_t ob2 = ob + (size_t)8 * INNER;
        *(uint32_t*)&oh[ob2] = hi2(a2, a3);
        *(uint32_t*)&ol[ob2] = lo2(a2, a3);
    }
}

// ---------------- launch -----------------------------------------------------
extern "C" void kernel_launch(void* const* d_in, const int* in_sizes, int n_in,
                              void* d_out, int out_size) {
    const float* x     = (const float*)d_in[0];
    const float* gamma = (const float*)d_in[1];
    const float* beta  = (const float*)d_in[2];
    const float* w_qkv = (const float*)d_in[3];
    const float* w_out = (const float*)d_in[4];
    const float* b_out = (const float*)d_in[5];
    float* out = (float*)d_out;

    bf16 *xnh, *xnl, *wqh, *wql, *woh, *wol;
    bf16 *qh, *ql, *kh, *kl, *vh, *vl, *ah, *al;
    float* qkv;
    cudaGetSymbolAddress((void**)&xnh, g_xn_hi);
    cudaGetSymbolAddress((void**)&xnl, g_xn_lo);
    cudaGetSymbolAddress((void**)&wqh, g_wqt_hi);
    cudaGetSymbolAddress((void**)&wql, g_wqt_lo);
    cudaGetSymbolAddress((void**)&woh, g_wot_hi);
    cudaGetSymbolAddress((void**)&wol, g_wot_lo);
    cudaGetSymbolAddress((void**)&qkv, g_qkv);
    cudaGetSymbolAddress((void**)&qh, g_q_hi);
    cudaGetSymbolAddress((void**)&ql, g_q_lo);
    cudaGetSymbolAddress((void**)&kh, g_k_hi);
    cudaGetSymbolAddress((void**)&kl, g_k_lo);
    cudaGetSymbolAddress((void**)&vh, g_v_hi);
    cudaGetSymbolAddress((void**)&vl, g_v_lo);
    cudaGetSymbolAddress((void**)&ah, g_att_hi);
    cudaGetSymbolAddress((void**)&al, g_att_lo);

    const int GEMM_SMEM = 98304;   // 3 stages x 32768B  -> 2 CTAs/SM
    const int ATTN_SMEM = 98304;   // Q 32768 + 2 KV stages x 32768 -> 2 CTAs/SM
    cudaFuncSetAttribute(gemm_kernel<false>,
                         cudaFuncAttributeMaxDynamicSharedMemorySize, GEMM_SMEM);
    cudaFuncSetAttribute(gemm_kernel<true>,
                         cudaFuncAttributeMaxDynamicSharedMemorySize, GEMM_SMEM);
    cudaFuncSetAttribute(attn_kernel,
                         cudaFuncAttributeMaxDynamicSharedMemorySize, ATTN_SMEM);

    // 1) LayerNorm -> split bf16
    ln_split_kernel<<<T, 256>>>(x, gamma, beta, xnh, xnl);
    // 2) weight transposes + splits
    transpose_split_kernel<<<dim3(3 * INNER / 32, DIM / 32), dim3(32, 8)>>>(
        w_qkv, wqh, wql, DIM, 3 * INNER);
    transpose_split_kernel<<<dim3(DIM / 32, INNER / 32), dim3(32, 8)>>>(
        w_out, woh, wol, INNER, DIM);
    // 3) QKV GEMM (fp32 out)
    gemm_kernel<false><<<dim3(3 * INNER / 128, T / 128), 256, GEMM_SMEM>>>(
        xnh, xnl, wqh, wql, nullptr, qkv, T, 3 * INNER, DIM);
    // 4) RoPE + split + relayout
    rope_convert_kernel<<<(T * HEADS * 32 + 255) / 256, 256>>>(
        qkv, qh, ql, kh, kl, vh, vl);
    // 5) Attention (tensor-core bf16x3)
    attn_kernel<<<dim3(SEQ / 128, HEADS, BATCH), 256, ATTN_SMEM>>>(
        qh, ql, kh, kl, vh, vl, ah, al);
    // 6) Output projection + bias
    gemm_kernel<true><<<dim3(DIM / 128, T / 128), 256, GEMM_SMEM>>>(
        ah, al, woh, wol, b_out, out, T, DIM, INNER);
}

// round 14
// speedup vs baseline: 3.3208x; 1.0090x over previous
#include <cuda_runtime.h>
#include <cuda_bf16.h>
#include <math.h>
#include <stdint.h>

#define DIM   1024
#define HEADS 16
#define DH    64
#define INNER 1024
#define BATCH 4
#define SEQ   2048
#define T     (BATCH * SEQ)   // 8192 tokens

typedef __nv_bfloat16 bf16;

// ---------------- scratch (device globals) ----------------------------------
__device__ bf16  g_xn_hi[T * DIM],        g_xn_lo[T * DIM];
__device__ bf16  g_wqt_hi[3 * INNER * DIM], g_wqt_lo[3 * INNER * DIM]; // [N][K]
__device__ bf16  g_wot_hi[DIM * INNER],   g_wot_lo[DIM * INNER];       // [N][K]
__device__ bf16  g_q_hi[T * INNER], g_q_lo[T * INNER];  // [b][h][n][d]
__device__ bf16  g_k_hi[T * INNER], g_k_lo[T * INNER];
__device__ bf16  g_v_hi[T * INNER], g_v_lo[T * INNER];
__device__ bf16  g_att_hi[T * INNER], g_att_lo[T * INNER]; // [t][h*64+d]
__device__ float g_cos[SEQ * 32], g_sin[SEQ * 32];

// ---------------- helpers ----------------------------------------------------
__device__ __forceinline__ uint32_t pack2(bf16 a, bf16 b) {
    return (uint32_t)__bfloat16_as_ushort(a) |
           ((uint32_t)__bfloat16_as_ushort(b) << 16);
}
__device__ __forceinline__ void split2(float x, bf16& h, bf16& l) {
    h = __float2bfloat16(x);
    l = __float2bfloat16(x - __bfloat162float(h));
}
__device__ __forceinline__ uint32_t hi2(float a, float b) {
    return pack2(__float2bfloat16(a), __float2bfloat16(b));
}
__device__ __forceinline__ uint32_t lo2(float a, float b) {
    bf16 ha = __float2bfloat16(a), hb = __float2bfloat16(b);
    return pack2(__float2bfloat16(a - __bfloat162float(ha)),
                 __float2bfloat16(b - __bfloat162float(hb)));
}
__device__ __forceinline__ void mma16816(float c[4], const uint32_t a[4],
                                         const uint32_t b[2]) {
    asm volatile(
        "mma.sync.aligned.m16n8k16.row.col.f32.bf16.bf16.f32 "
        "{%0,%1,%2,%3}, {%4,%5,%6,%7}, {%8,%9}, {%0,%1,%2,%3};\n"
        : "+f"(c[0]), "+f"(c[1]), "+f"(c[2]), "+f"(c[3])
        : "r"(a[0]), "r"(a[1]), "r"(a[2]), "r"(a[3]), "r"(b[0]), "r"(b[1]));
}
__device__ __forceinline__ void ldsm4(uint32_t r[4], uint32_t addr) {
    asm volatile("ldmatrix.sync.aligned.m8n8.x4.shared.b16 {%0,%1,%2,%3}, [%4];"
        : "=r"(r[0]), "=r"(r[1]), "=r"(r[2]), "=r"(r[3]) : "r"(addr));
}
__device__ __forceinline__ void ldsm4t(uint32_t r[4], uint32_t addr) {
    asm volatile("ldmatrix.sync.aligned.m8n8.x4.trans.shared.b16 {%0,%1,%2,%3}, [%4];"
        : "=r"(r[0]), "=r"(r[1]), "=r"(r[2]), "=r"(r[3]) : "r"(addr));
}
__device__ __forceinline__ void cpa16(uint32_t dst, const void* src) {
    asm volatile("cp.async.cg.shared.global [%0], [%1], 16;" :: "r"(dst), "l"(src));
}
#define CP_COMMIT asm volatile("cp.async.commit_group;" ::: "memory")
#define CP_WAIT1  asm volatile("cp.async.wait_group 1;" ::: "memory")
#define CP_WAIT2  asm volatile("cp.async.wait_group 2;" ::: "memory")

// XOR swizzles
__device__ __forceinline__ uint32_t sw64(uint32_t row, uint32_t chunk) {
    return row * 64u + ((chunk ^ ((row >> 1) & 3u)) * 16u);
}
__device__ __forceinline__ uint32_t sw128(uint32_t row, uint32_t chunk) {
    return row * 128u + ((chunk ^ (row & 7u)) * 16u);
}

// ---------------- LayerNorm -> split bf16 ------------------------------------
__global__ void ln_split_kernel(const float* __restrict__ x,
                                const float* __restrict__ gamma,
                                const float* __restrict__ beta,
                                bf16* __restrict__ xh, bf16* __restrict__ xl) {
    int t = blockIdx.x, tid = threadIdx.x;
    const float4 v = ((const float4*)(x + (size_t)t * DIM))[tid];
    float s  = v.x + v.y + v.z + v.w;
    float ss = v.x * v.x + v.y * v.y + v.z * v.z + v.w * v.w;
#pragma unroll
    for (int o = 16; o; o >>= 1) {
        s  += __shfl_xor_sync(0xffffffffu, s,  o);
        ss += __shfl_xor_sync(0xffffffffu, ss, o);
    }
    __shared__ float rs[8], rq[8], stats[2];
    if ((tid & 31) == 0) { rs[tid >> 5] = s; rq[tid >> 5] = ss; }
    __syncthreads();
    if (tid == 0) {
        float a = 0.f, b2 = 0.f;
#pragma unroll
        for (int i = 0; i < 8; i++) { a += rs[i]; b2 += rq[i]; }
        float mu  = a * (1.f / DIM);
        float var = b2 * (1.f / DIM) - mu * mu;
        stats[0] = mu; stats[1] = rsqrtf(var + 1e-5f);
    }
    __syncthreads();
    float mu = stats[0], inv = stats[1];
    const float4 g  = ((const float4*)gamma)[tid];
    const float4 be = ((const float4*)beta)[tid];
    float o0 = (v.x - mu) * inv * g.x + be.x;
    float o1 = (v.y - mu) * inv * g.y + be.y;
    float o2 = (v.z - mu) * inv * g.z + be.z;
    float o3 = (v.w - mu) * inv * g.w + be.w;
    size_t o = (size_t)t * DIM + tid * 4;
    uint2 h = make_uint2(hi2(o0, o1), hi2(o2, o3));
    uint2 l = make_uint2(lo2(o0, o1), lo2(o2, o3));
    *(uint2*)&xh[o] = h;
    *(uint2*)&xl[o] = l;
}

// ---------------- transpose + split weights ----------------------------------
__global__ void transpose_split_kernel(const float* __restrict__ w,
                                       bf16* __restrict__ wh,
                                       bf16* __restrict__ wl, int K, int N) {
    __shared__ float tile[32][33];
    int n0 = blockIdx.x * 32, k0 = blockIdx.y * 32;
    int tx = threadIdx.x, ty = threadIdx.y;  // 32 x 8
#pragma unroll
    for (int i = 0; i < 32; i += 8)
        tile[ty + i][tx] = w[(size_t)(k0 + ty + i) * N + n0 + tx];
    __syncthreads();
#pragma unroll
    for (int i = 0; i < 32; i += 8) {
        float v = tile[tx][ty + i];
        bf16 h, l; split2(v, h, l);
        size_t o = (size_t)(n0 + ty + i) * K + k0 + tx;
        wh[o] = h; wl[o] = l;
    }
}

// ---------------- RoPE cos/sin table -----------------------------------------
__global__ void rope_table_kernel(float* __restrict__ ctab,
                                  float* __restrict__ stab) {
    int idx = blockIdx.x * 256 + threadIdx.x;
    if (idx >= SEQ * 32) return;
    int pos = idx >> 5, i = idx & 31;
    float inv = exp2f(-(float)i * (13.287712379549449f / 32.f));
    float sn, cs;
    sincosf((float)pos * inv, &sn, &cs);
    ctab[idx] = cs; stab[idx] = sn;
}

// ---------------- bf16x3 GEMM (cp.async 3-stage, swizzled, 2 CTA/SM) ---------
// C[M,N] = A[M,K] @ Bt[N,K]^T. BM=BN=128, BK=32, 8 warps (4x2).
// FUSE_ROPE: instead of fp32 C, apply RoPE (q,k) + split + head-major store.
template <bool HAS_BIAS, bool FUSE_ROPE>
__global__ __launch_bounds__(256, 2)
void gemm_kernel(const bf16* __restrict__ Agh, const bf16* __restrict__ Agl,
                 const bf16* __restrict__ Bgh, const bf16* __restrict__ Bgl,
                 const float* __restrict__ bias, float* __restrict__ C,
                 int M, int N, int K,
                 bf16* __restrict__ qh_, bf16* __restrict__ ql_,
                 bf16* __restrict__ kh_, bf16* __restrict__ kl_,
                 bf16* __restrict__ vh_, bf16* __restrict__ vl_,
                 const float* __restrict__ ctab, const float* __restrict__ stab) {
    extern __shared__ __align__(16) unsigned char sm[];
    uint32_t smb = (uint32_t)__cvta_generic_to_shared(sm);
    const int tid = threadIdx.x;
    const int wid = tid >> 5, lane = tid & 31;
    const int wm = wid >> 1, wn = wid & 1;
    const int g = lane >> 2, t2 = (lane & 3) * 2;
    const int within = lane & 7, grp = lane >> 3;
    const int m0 = blockIdx.y * 128, n0 = blockIdx.x * 128;
    const int r = tid >> 1, c2 = (tid & 1) * 2;
    const int NIT = K >> 5;

    float acc[2][8][4];
#pragma unroll
    for (int i = 0; i < 2; i++)
#pragma unroll
        for (int j = 0; j < 8; j++)
#pragma unroll
            for (int k = 0; k < 4; k++) acc[i][j][k] = 0.f;

    auto issue = [&](int it) {
        int k0 = it << 5;
        uint32_t sb = smb + (uint32_t)(it % 3) * 32768u;
        uint32_t o0 = sw64((uint32_t)r, (uint32_t)c2);
        uint32_t o1 = sw64((uint32_t)r, (uint32_t)c2 + 1);
        const bf16* p = Agh + (size_t)(m0 + r) * K + k0 + c2 * 8;
        cpa16(sb + o0, p);             cpa16(sb + o1, p + 8);
        p = Agl + (size_t)(m0 + r) * K + k0 + c2 * 8;
        cpa16(sb + 8192 + o0, p);      cpa16(sb + 8192 + o1, p + 8);
        p = Bgh + (size_t)(n0 + r) * K + k0 + c2 * 8;
        cpa16(sb + 16384 + o0, p);     cpa16(sb + 16384 + o1, p + 8);
        p = Bgl + (size_t)(n0 + r) * K + k0 + c2 * 8;
        cpa16(sb + 24576 + o0, p);     cpa16(sb + 24576 + o1, p + 8);
        CP_COMMIT;
    };
    issue(0); issue(1);

    for (int it = 0; it < NIT; it++) {
        CP_WAIT1;
        __syncthreads();
        if (it + 2 < NIT) issue(it + 2);
        uint32_t sb = smb + (uint32_t)(it % 3) * 32768u;
#pragma unroll
        for (int kk8 = 0; kk8 < 4; kk8 += 2) {
            uint32_t aH[2][4], aL[2][4], bH[8][2], bL[8][2];
#pragma unroll
            for (int mt = 0; mt < 2; mt++) {
                uint32_t ra = (uint32_t)(wm * 32 + mt * 16 + within + (grp & 1) * 8);
                uint32_t sa = (uint32_t)(kk8 + (grp >> 1));
                ldsm4(aH[mt], sb + sw64(ra, sa));
                ldsm4(aL[mt], sb + 8192u + sw64(ra, sa));
            }
#pragma unroll
            for (int ntp = 0; ntp < 4; ntp++) {
                uint32_t rb = (uint32_t)(wn * 64 + ntp * 16 + within + (grp >> 1) * 8);
                uint32_t sg = (uint32_t)(kk8 + (grp & 1));
                uint32_t t4[4];
                ldsm4(t4, sb + 16384u + sw64(rb, sg));
                bH[2 * ntp][0] = t4[0]; bH[2 * ntp][1] = t4[1];
                bH[2 * ntp + 1][0] = t4[2]; bH[2 * ntp + 1][1] = t4[3];
                ldsm4(t4, sb + 24576u + sw64(rb, sg));
                bL[2 * ntp][0] = t4[0]; bL[2 * ntp][1] = t4[1];
                bL[2 * ntp + 1][0] = t4[2]; bL[2 * ntp + 1][1] = t4[3];
            }
#pragma unroll
            for (int mt = 0; mt < 2; mt++)
#pragma unroll
                for (int nt = 0; nt < 8; nt++) {
                    mma16816(acc[mt][nt], aH[mt], bH[nt]);
                    mma16816(acc[mt][nt], aH[mt], bL[nt]);
                    mma16816(acc[mt][nt], aL[mt], bH[nt]);
                }
        }
    }

#pragma unroll
    for (int mt = 0; mt < 2; mt++) {
#pragma unroll
        for (int nt = 0; nt < 8; nt++) {
            int row = m0 + wm * 32 + mt * 16 + g;
            int col = n0 + wn * 64 + nt * 8 + t2;
            if (FUSE_ROPE) {
                // col -> section(q/k/v), head, dim; rows row and row+8
                int sec = col >> 10, c = col & 1023;
                int hh = c >> 6, d = c & 63, fi = d >> 1;
#pragma unroll
                for (int rr = 0; rr < 2; rr++) {
                    int t = row + rr * 8;
                    float e = acc[mt][nt][rr * 2], o = acc[mt][nt][rr * 2 + 1];
                    int pos = t & (SEQ - 1), bb = t >> 11;
                    size_t off = (((size_t)(bb * HEADS + hh)) * SEQ + pos) * DH + d;
                    if (sec == 2) {
                        *(uint32_t*)&vh_[off] = hi2(e, o);
                        *(uint32_t*)&vl_[off] = lo2(e, o);
                    } else {
                        float cs = ctab[pos * 32 + fi], sn = stab[pos * 32 + fi];
                        float e2 = e * cs - o * sn;
                        float o2 = e * sn + o * cs;
                        if (sec == 0) {
                            *(uint32_t*)&qh_[off] = hi2(e2, o2);
                            *(uint32_t*)&ql_[off] = lo2(e2, o2);
                        } else {
                            *(uint32_t*)&kh_[off] = hi2(e2, o2);
                            *(uint32_t*)&kl_[off] = lo2(e2, o2);
                        }
                    }
                }
            } else {
                float b0 = 0.f, b1 = 0.f;
                if (HAS_BIAS) { b0 = bias[col]; b1 = bias[col + 1]; }
                float2 v0 = make_float2(acc[mt][nt][0] + b0, acc[mt][nt][1] + b1);
                float2 v1 = make_float2(acc[mt][nt][2] + b0, acc[mt][nt][3] + b1);
                *(float2*)&C[(size_t)row * N + col] = v0;
                *(float2*)&C[(size_t)(row + 8) * N + col] = v1;
            }
        }
    }
}

// ---------------- Flash attention (bf16x3, 2-stage KV ring, 2 CTA/SM) --------
__global__ __launch_bounds__(256, 2)
void attn_kernel(const bf16* __restrict__ qgh, const bf16* __restrict__ qgl,
                 const bf16* __restrict__ kgh, const bf16* __restrict__ kgl,
                 const bf16* __restrict__ vgh, const bf16* __restrict__ vgl,
                 bf16* __restrict__ oh, bf16* __restrict__ ol) {
    extern __shared__ __align__(16) unsigned char sm[];
    uint32_t smb = (uint32_t)__cvta_generic_to_shared(sm);
    const uint32_t QH = 0, QL = 16384, KV0 = 32768, KVS = 32768;

    const int tid = threadIdx.x, wid = tid >> 5, lane = tid & 31;
    const int g = lane >> 2, t2 = (lane & 3) * 2;
    const int within = lane & 7, grp = lane >> 3;
    const int b = blockIdx.z, h = blockIdx.y;
    const int q0 = blockIdx.x * 128;
    const size_t hb = (size_t)(b * HEADS + h) * SEQ * DH;

    {
        int rq = tid >> 1, c4 = (tid & 1) * 4;
        const bf16* ph = qgh + hb + (size_t)(q0 + rq) * DH + c4 * 8;
        const bf16* pl = qgl + hb + (size_t)(q0 + rq) * DH + c4 * 8;
#pragma unroll
        for (int cc = 0; cc < 4; cc++) {
            uint32_t off = sw128((uint32_t)rq, (uint32_t)(c4 + cc));
            cpa16(smb + QH + off, ph + cc * 8);
            cpa16(smb + QL + off, pl + cc * 8);
        }
        CP_COMMIT;
    }
    const int rkv = tid >> 2, ckv = (tid & 3) * 2;
    auto issueKV = [&](int j) {
        uint32_t sb = smb + KV0 + (uint32_t)(j & 1) * KVS;
        uint32_t o0 = sw128((uint32_t)rkv, (uint32_t)ckv);
        uint32_t o1 = sw128((uint32_t)rkv, (uint32_t)ckv + 1);
        const bf16* p = kgh + hb + (size_t)(j * 64 + rkv) * DH + ckv * 8;
        cpa16(sb + o0, p);             cpa16(sb + o1, p + 8);
        p = kgl + hb + (size_t)(j * 64 + rkv) * DH + ckv * 8;
        cpa16(sb + 8192 + o0, p);      cpa16(sb + 8192 + o1, p + 8);
        p = vgh + hb + (size_t)(j * 64 + rkv) * DH + ckv * 8;
        cpa16(sb + 16384 + o0, p);     cpa16(sb + 16384 + o1, p + 8);
        p = vgl + hb + (size_t)(j * 64 + rkv) * DH + ckv * 8;
        cpa16(sb + 24576 + o0, p);     cpa16(sb + 24576 + o1, p + 8);
        CP_COMMIT;
    };
    issueKV(0); issueKV(1);

    CP_WAIT2;
    __syncthreads();

    uint32_t qH[4][4], qL[4][4];
    const int qr = wid * 16;
#pragma unroll
    for (int kk4 = 0; kk4 < 4; kk4++) {
        uint32_t ra = (uint32_t)(qr + within + (grp & 1) * 8);
        uint32_t sa = (uint32_t)(kk4 * 2 + (grp >> 1));
        ldsm4(qH[kk4], smb + QH + sw128(ra, sa));
        ldsm4(qL[kk4], smb + QL + sw128(ra, sa));
    }

    float m0v = -1e30f, m1v = -1e30f, l0v = 0.f, l1v = 0.f;
    float oacc[8][4];
#pragma unroll
    for (int i = 0; i < 8; i++)
#pragma unroll
        for (int j = 0; j < 4; j++) oacc[i][j] = 0.f;

    const int NJ = SEQ / 64;
    for (int j = 0; j < NJ; j++) {
        CP_WAIT1;
        __syncthreads();
        uint32_t sb = smb + KV0 + (uint32_t)(j & 1) * KVS;

        float sacc[8][4];
#pragma unroll
        for (int i = 0; i < 8; i++)
#pragma unroll
            for (int jj = 0; jj < 4; jj++) sacc[i][jj] = 0.f;
#pragma unroll
        for (int kk4 = 0; kk4 < 4; kk4++) {
#pragma unroll
            for (int ntp = 0; ntp < 4; ntp++) {
                uint32_t rb = (uint32_t)(ntp * 16 + within + (grp >> 1) * 8);
                uint32_t sg = (uint32_t)(kk4 * 2 + (grp & 1));
                uint32_t t4[4], u4[4];
                ldsm4(t4, sb + sw128(rb, sg));
                ldsm4(u4, sb + 8192u + sw128(rb, sg));
                uint32_t bh0[2] = {t4[0], t4[1]}, bh1[2] = {t4[2], t4[3]};
                uint32_t bl0[2] = {u4[0], u4[1]}, bl1[2] = {u4[2], u4[3]};
                mma16816(sacc[2 * ntp],     qH[kk4], bh0);
                mma16816(sacc[2 * ntp],     qH[kk4], bl0);
                mma16816(sacc[2 * ntp],     qL[kk4], bh0);
                mma16816(sacc[2 * ntp + 1], qH[kk4], bh1);
                mma16816(sacc[2 * ntp + 1], qH[kk4], bl1);
                mma16816(sacc[2 * ntp + 1], qL[kk4], bh1);
            }
        }

        const float scale = 0.125f;
        float mx0 = -1e30f, mx1 = -1e30f;
#pragma unroll
        for (int nt = 0; nt < 8; nt++) {
#pragma unroll
            for (int jj = 0; jj < 4; jj++) sacc[nt][jj] *= scale;
            mx0 = fmaxf(mx0, fmaxf(sacc[nt][0], sacc[nt][1]));
            mx1 = fmaxf(mx1, fmaxf(sacc[nt][2], sacc[nt][3]));
        }
#pragma unroll
        for (int o = 1; o <= 2; o <<= 1) {
            mx0 = fmaxf(mx0, __shfl_xor_sync(0xffffffffu, mx0, o));
            mx1 = fmaxf(mx1, __shfl_xor_sync(0xffffffffu, mx1, o));
        }
        float mn0 = fmaxf(m0v, mx0), mn1 = fmaxf(m1v, mx1);
        float al0 = __expf(m0v - mn0), al1 = __expf(m1v - mn1);
        float sum0 = 0.f, sum1 = 0.f;
#pragma unroll
        for (int nt = 0; nt < 8; nt++) {
            sacc[nt][0] = __expf(sacc[nt][0] - mn0);
            sacc[nt][1] = __expf(sacc[nt][1] - mn0);
            sacc[nt][2] = __expf(sacc[nt][2] - mn1);
            sacc[nt][3] = __expf(sacc[nt][3] - mn1);
            sum0 += sacc[nt][0] + sacc[nt][1];
            sum1 += sacc[nt][2] + sacc[nt][3];
        }
#pragma unroll
        for (int o = 1; o <= 2; o <<= 1) {
            sum0 += __shfl_xor_sync(0xffffffffu, sum0, o);
            sum1 += __shfl_xor_sync(0xffffffffu, sum1, o);
        }
        l0v = l0v * al0 + sum0; m0v = mn0;
        l1v = l1v * al1 + sum1; m1v = mn1;
#pragma unroll
        for (int nt = 0; nt < 8; nt++) {
            oacc[nt][0] *= al0; oacc[nt][1] *= al0;
            oacc[nt][2] *= al1; oacc[nt][3] *= al1;
        }

#pragma unroll
        for (int kt = 0; kt < 4; kt++) {
            uint32_t pH[4], pL[4];
            pH[0] = hi2(sacc[2 * kt][0],     sacc[2 * kt][1]);
            pH[1] = hi2(sacc[2 * kt][2],     sacc[2 * kt][3]);
            pH[2] = hi2(sacc[2 * kt + 1][0], sacc[2 * kt + 1][1]);
            pH[3] = hi2(sacc[2 * kt + 1][2], sacc[2 * kt + 1][3]);
            pL[0] = lo2(sacc[2 * kt][0],     sacc[2 * kt][1]);
            pL[1] = lo2(sacc[2 * kt][2],     sacc[2 * kt][3]);
            pL[2] = lo2(sacc[2 * kt + 1][0], sacc[2 * kt + 1][1]);
            pL[3] = lo2(sacc[2 * kt + 1][2], sacc[2 * kt + 1][3]);
#pragma unroll
            for (int ntp = 0; ntp < 4; ntp++) {
                uint32_t tok = (uint32_t)(kt * 16 + within + (grp & 1) * 8);
                uint32_t sg  = (uint32_t)(ntp * 2 + (grp >> 1));
                uint32_t t4[4], u4[4];
                ldsm4t(t4, sb + 16384u + sw128(tok, sg));
                ldsm4t(u4, sb + 24576u + sw128(tok, sg));
                uint32_t bh0[2] = {t4[0], t4[1]}, bh1[2] = {t4[2], t4[3]};
                uint32_t bl0[2] = {u4[0], u4[1]}, bl1[2] = {u4[2], u4[3]};
                mma16816(oacc[2 * ntp],     pH, bh0);
                mma16816(oacc[2 * ntp],     pH, bl0);
                mma16816(oacc[2 * ntp],     pL, bh0);
                mma16816(oacc[2 * ntp + 1], pH, bh1);
                mma16816(oacc[2 * ntp + 1], pH, bl1);
                mma16816(oacc[2 * ntp + 1], pL, bh1);
            }
        }

        __syncthreads();
        if (j + 2 < NJ) issueKV(j + 2);
    }

    float i0 = 1.f / l0v, i1 = 1.f / l1v;
#pragma unroll
    for (int nt = 0; nt < 8; nt++) {
        int row = q0 + qr + g;
        int col = h * DH + nt * 8 + t2;
        size_t ob = (size_t)(b * SEQ + row) * INNER + col;
        float a0 = oacc[nt][0] * i0, a1 = oacc[nt][1] * i0;
        float a2 = oacc[nt][2] * i1, a3 = oacc[nt][3] * i1;
        *(uint32_t*)&oh[ob] = hi2(a0, a1);
        *(uint32_t*)&ol[ob] = lo2(a0, a1);
        size_t ob2 = ob + (size_t)8 * INNER;
        *(uint32_t*)&oh[ob2] = hi2(a2, a3);
        *(uint32_t*)&ol[ob2] = lo2(a2, a3);
    }
}

// ---------------- launch -----------------------------------------------------
extern "C" void kernel_launch(void* const* d_in, const int* in_sizes, int n_in,
                              void* d_out, int out_size) {
    const float* x     = (const float*)d_in[0];
    const float* gamma = (const float*)d_in[1];
    const float* beta  = (const float*)d_in[2];
    const float* w_qkv = (const float*)d_in[3];
    const float* w_out = (const float*)d_in[4];
    const float* b_out = (const float*)d_in[5];
    float* out = (float*)d_out;

    bf16 *xnh, *xnl, *wqh, *wql, *woh, *wol;
    bf16 *qh, *ql, *kh, *kl, *vh, *vl, *ah, *al;
    float *ctab, *stab;
    cudaGetSymbolAddress((void**)&xnh, g_xn_hi);
    cudaGetSymbolAddress((void**)&xnl, g_xn_lo);
    cudaGetSymbolAddress((void**)&wqh, g_wqt_hi);
    cudaGetSymbolAddress((void**)&wql, g_wqt_lo);
    cudaGetSymbolAddress((void**)&woh, g_wot_hi);
    cudaGetSymbolAddress((void**)&wol, g_wot_lo);
    cudaGetSymbolAddress((void**)&qh, g_q_hi);
    cudaGetSymbolAddress((void**)&ql, g_q_lo);
    cudaGetSymbolAddress((void**)&kh, g_k_hi);
    cudaGetSymbolAddress((void**)&kl, g_k_lo);
    cudaGetSymbolAddress((void**)&vh, g_v_hi);
    cudaGetSymbolAddress((void**)&vl, g_v_lo);
    cudaGetSymbolAddress((void**)&ah, g_att_hi);
    cudaGetSymbolAddress((void**)&al, g_att_lo);
    cudaGetSymbolAddress((void**)&ctab, g_cos);
    cudaGetSymbolAddress((void**)&stab, g_sin);

    const int GEMM_SMEM = 98304;   // 3 stages x 32768B  -> 2 CTAs/SM
    const int ATTN_SMEM = 98304;   // Q 32768 + 2 KV stages x 32768 -> 2 CTAs/SM
    cudaFuncSetAttribute((const void*)gemm_kernel<false, true>,
                         cudaFuncAttributeMaxDynamicSharedMemorySize, GEMM_SMEM);
    cudaFuncSetAttribute((const void*)gemm_kernel<true, false>,
                         cudaFuncAttributeMaxDynamicSharedMemorySize, GEMM_SMEM);
    cudaFuncSetAttribute((const void*)attn_kernel,
                         cudaFuncAttributeMaxDynamicSharedMemorySize, ATTN_SMEM);

    // 1) LayerNorm -> split bf16
    ln_split_kernel<<<T, 256>>>(x, gamma, beta, xnh, xnl);
    // 2) weight transposes + splits, RoPE table
    transpose_split_kernel<<<dim3(3 * INNER / 32, DIM / 32), dim3(32, 8)>>>(
        w_qkv, wqh, wql, DIM, 3 * INNER);
    transpose_split_kernel<<<dim3(DIM / 32, INNER / 32), dim3(32, 8)>>>(
        w_out, woh, wol, INNER, DIM);
    rope_table_kernel<<<(SEQ * 32 + 255) / 256, 256>>>(ctab, stab);
    // 3) QKV GEMM with fused RoPE + split + head-major relayout
    gemm_kernel<false, true><<<dim3(3 * INNER / 128, T / 128), 256, GEMM_SMEM>>>(
        xnh, xnl, wqh, wql, nullptr, nullptr, T, 3 * INNER, DIM,
        qh, ql, kh, kl, vh, vl, ctab, stab);
    // 4) Attention (mma.sync bf16x3)
    attn_kernel<<<dim3(SEQ / 128, HEADS, BATCH), 256, ATTN_SMEM>>>(
        qh, ql, kh, kl, vh, vl, ah, al);
    // 5) Output projection + bias
    gemm_kernel<true, false><<<dim3(DIM / 128, T / 128), 256, GEMM_SMEM>>>(
        ah, al, woh, wol, b_out, out, T, DIM, INNER,
        nullptr, nullptr, nullptr, nullptr, nullptr, nullptr, nullptr, nullptr);
}